// round 8
// baseline (speedup 1.0000x reference)
#include <cuda_runtime.h>
#include <cuda_bf16.h>
#include <mma.h>
#include <math.h>
#include <cstdint>

using namespace nvcuda;

#define T_  4096
#define NF_ 256
#define DH_ 64
#define BH_ 64
#define DS  0.35355339059327373f
#define DNC 0.0625f

// Scratch (static __device__ — no allocations allowed)
__device__ float g_kp[(size_t)BH_ * T_ * NF_];   // 268 MB
__device__ float g_ctx[BH_ * NF_ * DH_];         // 4 MB, layout [bh][e][j] (transposed)
__device__ float g_ksum[BH_ * NF_];

__device__ __forceinline__ uint32_t packb(__nv_bfloat16 a, __nv_bfloat16 b) {
  __nv_bfloat162 t(a, b);
  return *reinterpret_cast<uint32_t*>(&t);
}

// Convert float4 -> bf16 hi + bf16 residual lo, store 4 elements each.
__device__ __forceinline__ void cvt_store(float4 v, __nv_bfloat16* hi,
                                          __nv_bfloat16* lo, int idx) {
  __nv_bfloat16 h0 = __float2bfloat16(v.x), h1 = __float2bfloat16(v.y);
  __nv_bfloat16 h2 = __float2bfloat16(v.z), h3 = __float2bfloat16(v.w);
  *(uint2*)(hi + idx) = make_uint2(packb(h0, h1), packb(h2, h3));
  __nv_bfloat16 l0 = __float2bfloat16(v.x - __bfloat162float(h0));
  __nv_bfloat16 l1 = __float2bfloat16(v.y - __bfloat162float(h1));
  __nv_bfloat16 l2 = __float2bfloat16(v.z - __bfloat162float(h2));
  __nv_bfloat16 l3 = __float2bfloat16(v.w - __bfloat162float(h3));
  *(uint2*)(lo + idx) = make_uint2(packb(l0, l1), packb(l2, l3));
}

// ---------------------------------------------------------------------------
__global__ void zero_kernel() {
  int idx = blockIdx.x * blockDim.x + threadIdx.x;
  const int n = BH_ * NF_ * DH_;
  for (int i = idx; i < n; i += gridDim.x * blockDim.x) g_ctx[i] = 0.f;
  if (idx < BH_ * NF_) g_ksum[idx] = 0.f;
}

// ---------------------------------------------------------------------------
// Kernel A: kp' = exp(ds*(k @ proj^T) - |k|^2/16 - rowmax)  -> g_kp  (scalar)
__global__ __launch_bounds__(256) void kernelA(const float* __restrict__ kin,
                                               const float* __restrict__ proj) {
  extern __shared__ float s[];
  float* p_s   = s;
  float* k_s   = p_s + 64 * NF_;
  float* dn_s  = k_s + 64 * 64;
  float* off_s = dn_s + 64;
  float* rp_s  = off_s + 64;

  const int tid = threadIdx.x;
  const int bh  = blockIdx.y;
  const int t0  = blockIdx.x * 64;

  if (tid < 64) dn_s[tid] = 0.f;
  __syncthreads();

  {
    const float4* pg = (const float4*)(proj + tid * DH_);
#pragma unroll
    for (int c = 0; c < 16; c++) {
      float4 vv = pg[c];
      p_s[(4*c+0)*NF_ + tid] = vv.x;
      p_s[(4*c+1)*NF_ + tid] = vv.y;
      p_s[(4*c+2)*NF_ + tid] = vv.z;
      p_s[(4*c+3)*NF_ + tid] = vv.w;
    }
  }
  {
    const int r  = tid & 63;
    const int c0 = tid >> 6;
    const float* kg = kin + ((size_t)bh * T_ + t0 + r) * DH_;
#pragma unroll
    for (int it = 0; it < 4; it++) {
      int c = it * 4 + c0;
      float4 vv = *(const float4*)(kg + 4 * c);
      k_s[(4*c+0)*64 + r] = vv.x;
      k_s[(4*c+1)*64 + r] = vv.y;
      k_s[(4*c+2)*64 + r] = vv.z;
      k_s[(4*c+3)*64 + r] = vv.w;
      atomicAdd(&dn_s[r], vv.x*vv.x + vv.y*vv.y + vv.z*vv.z + vv.w*vv.w);
    }
  }
  __syncthreads();

  const int tc = tid & 31;
  const int tr = tid >> 5;
  float acc[8][8];
#pragma unroll
  for (int i = 0; i < 8; i++)
#pragma unroll
    for (int j = 0; j < 8; j++) acc[i][j] = 0.f;

#pragma unroll 4
  for (int d = 0; d < 64; d++) {
    float a[8], b[8];
    *(float4*)&a[0] = *(const float4*)&k_s[d*64 + tr*8];
    *(float4*)&a[4] = *(const float4*)&k_s[d*64 + tr*8 + 4];
    *(float4*)&b[0] = *(const float4*)&p_s[d*NF_ + tc*8];
    *(float4*)&b[4] = *(const float4*)&p_s[d*NF_ + tc*8 + 4];
#pragma unroll
    for (int i = 0; i < 8; i++)
#pragma unroll
      for (int j = 0; j < 8; j++) acc[i][j] = fmaf(a[i], b[j], acc[i][j]);
  }

#pragma unroll
  for (int i = 0; i < 8; i++) {
    float m = acc[i][0];
#pragma unroll
    for (int j = 1; j < 8; j++) m = fmaxf(m, acc[i][j]);
    rp_s[(tr*8 + i)*33 + tc] = m;
  }
  __syncthreads();
  if (tid < 64) {
    float m = rp_s[tid*33];
#pragma unroll
    for (int c = 1; c < 32; c++) m = fmaxf(m, rp_s[tid*33 + c]);
    off_s[tid] = DS * m + DNC * dn_s[tid];
  }
  __syncthreads();

  float* outp = g_kp + ((size_t)bh * T_ + t0) * NF_;
#pragma unroll
  for (int i = 0; i < 8; i++) {
    int r = tr*8 + i;
    float off = off_s[r];
    float o[8];
#pragma unroll
    for (int j = 0; j < 8; j++) o[j] = __expf(fmaf(DS, acc[i][j], -off));
    *(float4*)&outp[(size_t)r*NF_ + tc*8]     = *(float4*)&o[0];
    *(float4*)&outp[(size_t)r*NF_ + tc*8 + 4] = *(float4*)&o[4];
  }
}

// ---------------------------------------------------------------------------
// Kernel B: context TRANSPOSED: g_ctx[bh][e][j] += sum_t kp'[t][j] * v[t][e]
__global__ __launch_bounds__(256) void kernelB(const float* __restrict__ vin) {
  extern __shared__ float s[];
  float* kp_s = s;
  float* v_s  = s + 64 * NF_;

  const int tid   = threadIdx.x;
  const int bh    = blockIdx.y;
  const int tbase = blockIdx.x * 512;
  const int ec = tid & 7;
  const int jr = tid >> 3;

  float acc[8][8];
  float ksp[8];
#pragma unroll
  for (int i = 0; i < 8; i++) {
    ksp[i] = 0.f;
#pragma unroll
    for (int j = 0; j < 8; j++) acc[i][j] = 0.f;
  }

  for (int ch = 0; ch < 8; ch++) {
    int t0 = tbase + ch * 64;
    __syncthreads();
    {
      const float4* src = (const float4*)(g_kp + ((size_t)bh * T_ + t0) * NF_);
      float4* dst = (float4*)kp_s;
#pragma unroll
      for (int i = 0; i < 16; i++) dst[tid + 256*i] = src[tid + 256*i];
      const float4* vsrc = (const float4*)(vin + ((size_t)bh * T_ + t0) * DH_);
      float4* vdst = (float4*)v_s;
#pragma unroll
      for (int i = 0; i < 4; i++) vdst[tid + 256*i] = vsrc[tid + 256*i];
    }
    __syncthreads();
#pragma unroll 2
    for (int t = 0; t < 64; t++) {
      float a[8], b[8];
      *(float4*)&a[0] = *(const float4*)&kp_s[t*NF_ + jr*8];
      *(float4*)&a[4] = *(const float4*)&kp_s[t*NF_ + jr*8 + 4];
      *(float4*)&b[0] = *(const float4*)&v_s[t*64 + ec*8];
      *(float4*)&b[4] = *(const float4*)&v_s[t*64 + ec*8 + 4];
#pragma unroll
      for (int i = 0; i < 8; i++)
#pragma unroll
        for (int j = 0; j < 8; j++) acc[i][j] = fmaf(a[i], b[j], acc[i][j]);
      if (ec == 0) {
#pragma unroll
        for (int i = 0; i < 8; i++) ksp[i] += a[i];
      }
    }
  }

  float* ctx = g_ctx + bh * NF_ * DH_;
#pragma unroll
  for (int i = 0; i < 8; i++)
#pragma unroll
    for (int j = 0; j < 8; j++)
      atomicAdd(&ctx[(ec*8 + j)*NF_ + jr*8 + i], acc[i][j]);   // [e][j]
  if (ec == 0) {
#pragma unroll
    for (int i = 0; i < 8; i++) atomicAdd(&g_ksum[bh*NF_ + jr*8 + i], ksp[i]);
  }
}

// ---------------------------------------------------------------------------
// Kernel C (wmma/HMMA): per block 128 tokens, 256 threads (8 warps).
//   MMA1: dp[128,256] = q @ proj^T (bf16 hi/lo split, 3 products)
//   fused per j-tile: exp epilogue + denom + MMA2 accumulation in registers
//   MMA2: out[128,64] = qp @ ctx
// smem byte offsets:
#define OQHI  0
#define OQLO  16384
#define OPHI  32768
#define OPLO  65536
#define OCHI  98304
#define OCLO  131072
#define OSTG  163840     // per warp 2048: c1[16x16 f32] | qp_hi[16x16] | qp_lo[16x16]
#define OKS   180224
#define ODN   181248
#define SMEMC 181760

__global__ __launch_bounds__(256, 1)
void kernelC(const float* __restrict__ qin,
             const float* __restrict__ proj,
             float* __restrict__ outg) {
  extern __shared__ char smc[];
  __nv_bfloat16* q_hi = (__nv_bfloat16*)(smc + OQHI);
  __nv_bfloat16* q_lo = (__nv_bfloat16*)(smc + OQLO);
  __nv_bfloat16* p_hi = (__nv_bfloat16*)(smc + OPHI);
  __nv_bfloat16* p_lo = (__nv_bfloat16*)(smc + OPLO);
  __nv_bfloat16* c_hi = (__nv_bfloat16*)(smc + OCHI);
  __nv_bfloat16* c_lo = (__nv_bfloat16*)(smc + OCLO);
  float* ks_s = (float*)(smc + OKS);
  float* dn_s = (float*)(smc + ODN);

  const int tid  = threadIdx.x;
  const int warp = tid >> 5;
  const int lane = tid & 31;
  const int bh   = blockIdx.y;
  const int t0   = blockIdx.x * 128;

  // --- proj [256][64] -> bf16 hi/lo (row-major, ld=64) ---
  {
    const float4* pg = (const float4*)proj;
#pragma unroll
    for (int it = 0; it < 16; it++) {
      int i = tid + it * 256;
      cvt_store(pg[i], p_hi, p_lo, i * 4);
    }
  }
  // --- ctx [e=64][j=256] -> bf16 hi/lo (row-major, ld=256) ---
  {
    const float4* cg = (const float4*)(g_ctx + bh * NF_ * DH_);
#pragma unroll
    for (int it = 0; it < 16; it++) {
      int i = tid + it * 256;
      cvt_store(cg[i], c_hi, c_lo, i * 4);
    }
  }
  // --- q [128][64] -> bf16 hi/lo + per-row |q|^2 ---
  {
    const int rq = tid >> 1, half = tid & 1;
    const float4* qg = (const float4*)(qin + ((size_t)(bh * T_ + t0 + rq)) * DH_);
    float dsum = 0.f;
#pragma unroll
    for (int c = 0; c < 8; c++) {
      float4 v = qg[half * 8 + c];
      dsum += v.x*v.x + v.y*v.y + v.z*v.z + v.w*v.w;
      cvt_store(v, q_hi, q_lo, rq * 64 + half * 32 + c * 4);
    }
    dsum += __shfl_xor_sync(0xffffffff, dsum, 1);
    if (half == 0) dn_s[rq] = dsum;
  }
  ks_s[tid] = g_ksum[bh * NF_ + tid];
  __syncthreads();

  // --- preload A fragments (warp's 16-row block, 4 k-tiles, hi/lo) ---
  wmma::fragment<wmma::matrix_a, 16, 16, 16, __nv_bfloat16, wmma::row_major> a_hi[4], a_lo[4];
#pragma unroll
  for (int kt = 0; kt < 4; kt++) {
    wmma::load_matrix_sync(a_hi[kt], q_hi + (warp * 16) * 64 + kt * 16, 64);
    wmma::load_matrix_sync(a_lo[kt], q_lo + (warp * 16) * 64 + kt * 16, 64);
  }
  wmma::fragment<wmma::accumulator, 16, 16, 16, float> oacc[4];
#pragma unroll
  for (int e = 0; e < 4; e++) wmma::fill_fragment(oacc[e], 0.f);

  float* c1 = (float*)(smc + OSTG + warp * 2048);
  __nv_bfloat16* qp_hi = (__nv_bfloat16*)(smc + OSTG + warp * 2048 + 1024);
  __nv_bfloat16* qp_lo = qp_hi + 256;

  const int er  = lane >> 1;          // epilogue row within the 16x16 tile
  const int ec0 = (lane & 1) * 8;     // epilogue column base
  const float dnt = DNC * dn_s[warp * 16 + er];
  float denom = 0.f;

  for (int jt = 0; jt < 16; jt++) {
    // MMA1: dp tile (16 rows x 16 features)
    wmma::fragment<wmma::accumulator, 16, 16, 16, float> acc;
    wmma::fill_fragment(acc, 0.f);
#pragma unroll
    for (int kt = 0; kt < 4; kt++) {
      wmma::fragment<wmma::matrix_b, 16, 16, 16, __nv_bfloat16, wmma::col_major> b_hi, b_lo;
      wmma::load_matrix_sync(b_hi, p_hi + (jt * 16) * 64 + kt * 16, 64);
      wmma::load_matrix_sync(b_lo, p_lo + (jt * 16) * 64 + kt * 16, 64);
      wmma::mma_sync(acc, a_hi[kt], b_hi, acc);
      wmma::mma_sync(acc, a_lo[kt], b_hi, acc);
      wmma::mma_sync(acc, a_hi[kt], b_lo, acc);
    }
    wmma::store_matrix_sync(c1, acc, 16, wmma::mem_row_major);
    __syncwarp();

    // epilogue: qp = exp(DS*dp - dn); denom += qp*ksum; qp -> bf16 hi/lo staging
#pragma unroll
    for (int c = 0; c < 8; c++) {
      float x = c1[er * 16 + ec0 + c];
      float e = __expf(fmaf(DS, x, -dnt));
      denom = fmaf(e, ks_s[jt * 16 + ec0 + c], denom);
      __nv_bfloat16 h = __float2bfloat16(e);
      qp_hi[er * 16 + ec0 + c] = h;
      qp_lo[er * 16 + ec0 + c] = __float2bfloat16(e - __bfloat162float(h));
    }
    __syncwarp();

    // MMA2: accumulate out += qp_tile @ ctx[j-tile, :]
    wmma::fragment<wmma::matrix_a, 16, 16, 16, __nv_bfloat16, wmma::row_major> a2_hi, a2_lo;
    wmma::load_matrix_sync(a2_hi, qp_hi, 16);
    wmma::load_matrix_sync(a2_lo, qp_lo, 16);
#pragma unroll
    for (int et = 0; et < 4; et++) {
      wmma::fragment<wmma::matrix_b, 16, 16, 16, __nv_bfloat16, wmma::col_major> b2_hi, b2_lo;
      wmma::load_matrix_sync(b2_hi, c_hi + (et * 16) * 256 + jt * 16, 256);
      wmma::load_matrix_sync(b2_lo, c_lo + (et * 16) * 256 + jt * 16, 256);
      wmma::mma_sync(oacc[et], a2_hi, b2_hi, oacc[et]);
      wmma::mma_sync(oacc[et], a2_lo, b2_hi, oacc[et]);
      wmma::mma_sync(oacc[et], a2_hi, b2_lo, oacc[et]);
    }
    __syncwarp();   // before c1 reuse next iteration
  }

  // finalize: combine denom pair, scale, store
  denom += __shfl_xor_sync(0xffffffff, denom, 1);
  float inv = 1.f / denom;
  float* og = outg + ((size_t)(bh * T_ + t0 + warp * 16 + er)) * DH_;
#pragma unroll
  for (int et = 0; et < 4; et++) {
    wmma::store_matrix_sync(c1, oacc[et], 16, wmma::mem_row_major);
    __syncwarp();
    float4 oa = *(float4*)&c1[er * 16 + ec0];
    float4 ob = *(float4*)&c1[er * 16 + ec0 + 4];
    oa.x *= inv; oa.y *= inv; oa.z *= inv; oa.w *= inv;
    ob.x *= inv; ob.y *= inv; ob.z *= inv; ob.w *= inv;
    *(float4*)&og[et * 16 + ec0]     = oa;
    *(float4*)&og[et * 16 + ec0 + 4] = ob;
    __syncwarp();
  }
}

// ---------------------------------------------------------------------------
extern "C" void kernel_launch(void* const* d_in, const int* in_sizes, int n_in,
                              void* d_out, int out_size) {
  const float* q    = (const float*)d_in[0];
  const float* k    = (const float*)d_in[1];
  const float* v    = (const float*)d_in[2];
  const float* proj = (const float*)d_in[3];
  float* out = (float*)d_out;

  const int smemA = (64*NF_ + 64*64 + 64 + 64 + 64*33) * 4;
  const int smemB = (64*NF_ + 64*64) * 4;
  const int smemC = SMEMC;

  cudaFuncSetAttribute(kernelA, cudaFuncAttributeMaxDynamicSharedMemorySize, smemA);
  cudaFuncSetAttribute(kernelB, cudaFuncAttributeMaxDynamicSharedMemorySize, smemB);
  cudaFuncSetAttribute(kernelC, cudaFuncAttributeMaxDynamicSharedMemorySize, smemC);

  zero_kernel<<<256, 256>>>();
  kernelA<<<dim3(T_/64, BH_), 256, smemA>>>(k, proj);
  kernelB<<<dim3(8, BH_), 256, smemB>>>(v);
  kernelC<<<dim3(T_/128, BH_), 256, smemC>>>(q, proj, out);
}

// round 9
// speedup vs baseline: 1.6994x; 1.6994x over previous
#include <cuda_runtime.h>
#include <cuda_bf16.h>
#include <math.h>
#include <cstdint>

#define T_  4096
#define NF_ 256
#define DH_ 64
#define BH_ 64
#define DS  0.35355339059327373f
#define DNC 0.0625f

// Scratch (static __device__ — no allocations allowed)
__device__ float g_kp[(size_t)BH_ * T_ * NF_];   // 268 MB
__device__ float g_ctx[BH_ * NF_ * DH_];         // 4 MB, layout [bh][e][j]
__device__ float g_ksum[BH_ * NF_];

__device__ __forceinline__ uint32_t packb(__nv_bfloat16 a, __nv_bfloat16 b) {
  __nv_bfloat162 t(a, b);
  return *reinterpret_cast<uint32_t*>(&t);
}

__device__ __forceinline__ void cvt_hilo(float4 v, uint2& hi, uint2& lo) {
  __nv_bfloat16 h0 = __float2bfloat16(v.x), h1 = __float2bfloat16(v.y);
  __nv_bfloat16 h2 = __float2bfloat16(v.z), h3 = __float2bfloat16(v.w);
  hi = make_uint2(packb(h0, h1), packb(h2, h3));
  lo = make_uint2(packb(__float2bfloat16(v.x - __bfloat162float(h0)),
                        __float2bfloat16(v.y - __bfloat162float(h1))),
                  packb(__float2bfloat16(v.z - __bfloat162float(h2)),
                        __float2bfloat16(v.w - __bfloat162float(h3))));
}

// m16n8k16 row.col bf16 -> f32
__device__ __forceinline__ void mma_bf16(float* d, const uint32_t* a,
                                         const uint32_t* b, const float* c) {
  asm volatile(
      "mma.sync.aligned.m16n8k16.row.col.f32.bf16.bf16.f32 "
      "{%0,%1,%2,%3}, {%4,%5,%6,%7}, {%8,%9}, {%10,%11,%12,%13};"
      : "=f"(d[0]), "=f"(d[1]), "=f"(d[2]), "=f"(d[3])
      : "r"(a[0]), "r"(a[1]), "r"(a[2]), "r"(a[3]),
        "r"(b[0]), "r"(b[1]),
        "f"(c[0]), "f"(c[1]), "f"(c[2]), "f"(c[3]));
}

// ---------------------------------------------------------------------------
__global__ void zero_kernel() {
  int idx = blockIdx.x * blockDim.x + threadIdx.x;
  const int n = BH_ * NF_ * DH_;
  for (int i = idx; i < n; i += gridDim.x * blockDim.x) g_ctx[i] = 0.f;
  if (idx < BH_ * NF_) g_ksum[idx] = 0.f;
}

// ---------------------------------------------------------------------------
// Kernel A: kp' = exp(ds*(k @ proj^T) - |k|^2/16 - rowmax)  -> g_kp  (scalar)
__global__ __launch_bounds__(256) void kernelA(const float* __restrict__ kin,
                                               const float* __restrict__ proj) {
  extern __shared__ float s[];
  float* p_s   = s;
  float* k_s   = p_s + 64 * NF_;
  float* dn_s  = k_s + 64 * 64;
  float* off_s = dn_s + 64;
  float* rp_s  = off_s + 64;

  const int tid = threadIdx.x;
  const int bh  = blockIdx.y;
  const int t0  = blockIdx.x * 64;

  if (tid < 64) dn_s[tid] = 0.f;
  __syncthreads();

  {
    const float4* pg = (const float4*)(proj + tid * DH_);
#pragma unroll
    for (int c = 0; c < 16; c++) {
      float4 vv = pg[c];
      p_s[(4*c+0)*NF_ + tid] = vv.x;
      p_s[(4*c+1)*NF_ + tid] = vv.y;
      p_s[(4*c+2)*NF_ + tid] = vv.z;
      p_s[(4*c+3)*NF_ + tid] = vv.w;
    }
  }
  {
    const int r  = tid & 63;
    const int c0 = tid >> 6;
    const float* kg = kin + ((size_t)bh * T_ + t0 + r) * DH_;
#pragma unroll
    for (int it = 0; it < 4; it++) {
      int c = it * 4 + c0;
      float4 vv = *(const float4*)(kg + 4 * c);
      k_s[(4*c+0)*64 + r] = vv.x;
      k_s[(4*c+1)*64 + r] = vv.y;
      k_s[(4*c+2)*64 + r] = vv.z;
      k_s[(4*c+3)*64 + r] = vv.w;
      atomicAdd(&dn_s[r], vv.x*vv.x + vv.y*vv.y + vv.z*vv.z + vv.w*vv.w);
    }
  }
  __syncthreads();

  const int tc = tid & 31;
  const int tr = tid >> 5;
  float acc[8][8];
#pragma unroll
  for (int i = 0; i < 8; i++)
#pragma unroll
    for (int j = 0; j < 8; j++) acc[i][j] = 0.f;

#pragma unroll 4
  for (int d = 0; d < 64; d++) {
    float a[8], b[8];
    *(float4*)&a[0] = *(const float4*)&k_s[d*64 + tr*8];
    *(float4*)&a[4] = *(const float4*)&k_s[d*64 + tr*8 + 4];
    *(float4*)&b[0] = *(const float4*)&p_s[d*NF_ + tc*8];
    *(float4*)&b[4] = *(const float4*)&p_s[d*NF_ + tc*8 + 4];
#pragma unroll
    for (int i = 0; i < 8; i++)
#pragma unroll
      for (int j = 0; j < 8; j++) acc[i][j] = fmaf(a[i], b[j], acc[i][j]);
  }

#pragma unroll
  for (int i = 0; i < 8; i++) {
    float m = acc[i][0];
#pragma unroll
    for (int j = 1; j < 8; j++) m = fmaxf(m, acc[i][j]);
    rp_s[(tr*8 + i)*33 + tc] = m;
  }
  __syncthreads();
  if (tid < 64) {
    float m = rp_s[tid*33];
#pragma unroll
    for (int c = 1; c < 32; c++) m = fmaxf(m, rp_s[tid*33 + c]);
    off_s[tid] = DS * m + DNC * dn_s[tid];
  }
  __syncthreads();

  float* outp = g_kp + ((size_t)bh * T_ + t0) * NF_;
#pragma unroll
  for (int i = 0; i < 8; i++) {
    int r = tr*8 + i;
    float off = off_s[r];
    float o[8];
#pragma unroll
    for (int j = 0; j < 8; j++) o[j] = __expf(fmaf(DS, acc[i][j], -off));
    *(float4*)&outp[(size_t)r*NF_ + tc*8]     = *(float4*)&o[0];
    *(float4*)&outp[(size_t)r*NF_ + tc*8 + 4] = *(float4*)&o[4];
  }
}

// ---------------------------------------------------------------------------
// Kernel B: context TRANSPOSED: g_ctx[bh][e][j] += sum_t kp'[t][j] * v[t][e]
__global__ __launch_bounds__(256) void kernelB(const float* __restrict__ vin) {
  extern __shared__ float s[];
  float* kp_s = s;
  float* v_s  = s + 64 * NF_;

  const int tid   = threadIdx.x;
  const int bh    = blockIdx.y;
  const int tbase = blockIdx.x * 512;
  const int ec = tid & 7;
  const int jr = tid >> 3;

  float acc[8][8];
  float ksp[8];
#pragma unroll
  for (int i = 0; i < 8; i++) {
    ksp[i] = 0.f;
#pragma unroll
    for (int j = 0; j < 8; j++) acc[i][j] = 0.f;
  }

  for (int ch = 0; ch < 8; ch++) {
    int t0 = tbase + ch * 64;
    __syncthreads();
    {
      const float4* src = (const float4*)(g_kp + ((size_t)bh * T_ + t0) * NF_);
      float4* dst = (float4*)kp_s;
#pragma unroll
      for (int i = 0; i < 16; i++) dst[tid + 256*i] = src[tid + 256*i];
      const float4* vsrc = (const float4*)(vin + ((size_t)bh * T_ + t0) * DH_);
      float4* vdst = (float4*)v_s;
#pragma unroll
      for (int i = 0; i < 4; i++) vdst[tid + 256*i] = vsrc[tid + 256*i];
    }
    __syncthreads();
#pragma unroll 2
    for (int t = 0; t < 64; t++) {
      float a[8], b[8];
      *(float4*)&a[0] = *(const float4*)&kp_s[t*NF_ + jr*8];
      *(float4*)&a[4] = *(const float4*)&kp_s[t*NF_ + jr*8 + 4];
      *(float4*)&b[0] = *(const float4*)&v_s[t*64 + ec*8];
      *(float4*)&b[4] = *(const float4*)&v_s[t*64 + ec*8 + 4];
#pragma unroll
      for (int i = 0; i < 8; i++)
#pragma unroll
        for (int j = 0; j < 8; j++) acc[i][j] = fmaf(a[i], b[j], acc[i][j]);
      if (ec == 0) {
#pragma unroll
        for (int i = 0; i < 8; i++) ksp[i] += a[i];
      }
    }
  }

  float* ctx = g_ctx + bh * NF_ * DH_;
#pragma unroll
  for (int i = 0; i < 8; i++)
#pragma unroll
    for (int j = 0; j < 8; j++)
      atomicAdd(&ctx[(ec*8 + j)*NF_ + jr*8 + i], acc[i][j]);   // [e][j]
  if (ec == 0) {
#pragma unroll
    for (int i = 0; i < 8; i++) atomicAdd(&g_ksum[bh*NF_ + jr*8 + i], ksp[i]);
  }
}

// ---------------------------------------------------------------------------
// Kernel C (raw mma.sync, register-resident qp): 128 tokens/block, 8 warps.
// smem: q_hi/lo (16K each), proj_hi/lo (32K each), ctx_hi/lo (32K each), ks, dn
#define OQHI  0
#define OQLO  16384
#define OPHI  32768
#define OPLO  65536
#define OCHI  98304
#define OCLO  131072
#define OKS   163840
#define ODN   164864
#define SMEMC 165504

__global__ __launch_bounds__(256, 1)
void kernelC(const float* __restrict__ qin,
             const float* __restrict__ proj,
             float* __restrict__ outg) {
  extern __shared__ char smc[];
  float* ks_s = (float*)(smc + OKS);
  float* dn_s = (float*)(smc + ODN);

  const int tid  = threadIdx.x;
  const int warp = tid >> 5;
  const int lane = tid & 31;
  const int grp  = lane >> 2;   // 0..7
  const int qd   = lane & 3;    // 0..3
  const int bh   = blockIdx.y;
  const int t0   = blockIdx.x * 128;

  // --- proj [256][64] -> bf16 hi/lo, 128B swizzled rows ---
  {
    const float4* pg = (const float4*)proj;
#pragma unroll
    for (int it = 0; it < 16; it++) {
      int i = tid + it * 256;
      int row = i >> 4, kp = (i & 15) * 4;
      uint32_t off = (uint32_t)row*128 + (uint32_t)(((kp>>3) ^ (row&7)) << 4)
                   + (uint32_t)((kp&7)*2);
      uint2 hi, lo; cvt_hilo(pg[i], hi, lo);
      *(uint2*)(smc + OPHI + off) = hi;
      *(uint2*)(smc + OPLO + off) = lo;
    }
  }
  // --- ctx [64][256] -> bf16 hi/lo, 512B swizzled rows ---
  {
    const float4* cg = (const float4*)(g_ctx + bh * NF_ * DH_);
#pragma unroll
    for (int it = 0; it < 16; it++) {
      int i = tid + it * 256;
      int e = i >> 6, j4 = (i & 63) * 4;
      int ch = j4 >> 3;
      int swc = (ch & 24) | ((ch ^ e) & 7);
      uint32_t off = (uint32_t)e*512 + (uint32_t)(swc << 4) + (uint32_t)((j4&7)*2);
      uint2 hi, lo; cvt_hilo(cg[i], hi, lo);
      *(uint2*)(smc + OCHI + off) = hi;
      *(uint2*)(smc + OCLO + off) = lo;
    }
  }
  // --- q [128][64] -> bf16 hi/lo + per-row |q|^2 ---
  {
    const int rq = tid >> 1, half = tid & 1;
    const float4* qg = (const float4*)(qin + ((size_t)(bh * T_ + t0 + rq)) * DH_);
    float dsum = 0.f;
#pragma unroll
    for (int c = 0; c < 8; c++) {
      float4 v = qg[half*8 + c];
      dsum += v.x*v.x + v.y*v.y + v.z*v.z + v.w*v.w;
      int kp = half*32 + c*4;
      uint32_t off = (uint32_t)rq*128 + (uint32_t)(((kp>>3) ^ (rq&7)) << 4)
                   + (uint32_t)((kp&7)*2);
      uint2 hi, lo; cvt_hilo(v, hi, lo);
      *(uint2*)(smc + OQHI + off) = hi;
      *(uint2*)(smc + OQLO + off) = lo;
    }
    dsum += __shfl_xor_sync(0xffffffff, dsum, 1);
    if (half == 0) dn_s[rq] = dsum;
  }
  ks_s[tid] = g_ksum[bh * NF_ + tid];
  __syncthreads();

  const int r0 = warp * 16;
  // --- preload q A-fragments: 4 k-chunks x hi/lo ---
  uint32_t aq_hi[4][4], aq_lo[4][4];
#pragma unroll
  for (int kc = 0; kc < 4; kc++) {
    uint32_t c0 = (uint32_t)(((kc*2)     ^ grp) << 4);
    uint32_t c1 = (uint32_t)(((kc*2 + 1) ^ grp) << 4);
    uint32_t base0 = (uint32_t)(r0 + grp)     * 128u + (uint32_t)(qd * 4);
    uint32_t base1 = (uint32_t)(r0 + grp + 8) * 128u + (uint32_t)(qd * 4);
    aq_hi[kc][0] = *(uint32_t*)(smc + OQHI + base0 + c0);
    aq_hi[kc][1] = *(uint32_t*)(smc + OQHI + base1 + c0);
    aq_hi[kc][2] = *(uint32_t*)(smc + OQHI + base0 + c1);
    aq_hi[kc][3] = *(uint32_t*)(smc + OQHI + base1 + c1);
    aq_lo[kc][0] = *(uint32_t*)(smc + OQLO + base0 + c0);
    aq_lo[kc][1] = *(uint32_t*)(smc + OQLO + base1 + c0);
    aq_lo[kc][2] = *(uint32_t*)(smc + OQLO + base0 + c1);
    aq_lo[kc][3] = *(uint32_t*)(smc + OQLO + base1 + c1);
  }

  float oacc[8][4];
#pragma unroll
  for (int et = 0; et < 8; et++)
#pragma unroll
    for (int i = 0; i < 4; i++) oacc[et][i] = 0.f;

  float den0 = 0.f, den1 = 0.f;
  const float dnt0 = DNC * dn_s[r0 + grp];
  const float dnt1 = DNC * dn_s[r0 + grp + 8];

  for (int jt = 0; jt < 16; jt++) {
    const int j0 = jt * 16;
    float x0[4] = {0,0,0,0}, y0[4] = {0,0,0,0};
    float x1[4] = {0,0,0,0}, y1[4] = {0,0,0,0};
#pragma unroll
    for (int kc = 0; kc < 4; kc++) {
      uint32_t c0 = (uint32_t)(((kc*2)     ^ grp) << 4);
      uint32_t c1 = (uint32_t)(((kc*2 + 1) ^ grp) << 4);
      uint32_t rb0 = (uint32_t)(j0 + grp)     * 128u + (uint32_t)(qd * 4);
      uint32_t rb1 = (uint32_t)(j0 + 8 + grp) * 128u + (uint32_t)(qd * 4);
      uint32_t b0h[2] = { *(uint32_t*)(smc + OPHI + rb0 + c0),
                          *(uint32_t*)(smc + OPHI + rb0 + c1) };
      uint32_t b0l[2] = { *(uint32_t*)(smc + OPLO + rb0 + c0),
                          *(uint32_t*)(smc + OPLO + rb0 + c1) };
      uint32_t b1h[2] = { *(uint32_t*)(smc + OPHI + rb1 + c0),
                          *(uint32_t*)(smc + OPHI + rb1 + c1) };
      uint32_t b1l[2] = { *(uint32_t*)(smc + OPLO + rb1 + c0),
                          *(uint32_t*)(smc + OPLO + rb1 + c1) };
      mma_bf16(x0, aq_hi[kc], b0h, x0);
      mma_bf16(y0, aq_lo[kc], b0h, y0);
      mma_bf16(y0, aq_hi[kc], b0l, y0);
      mma_bf16(x1, aq_hi[kc], b1h, x1);
      mma_bf16(y1, aq_lo[kc], b1h, y1);
      mma_bf16(y1, aq_hi[kc], b1l, y1);
    }

    // epilogue in registers
    float e00 = __expf(fmaf(DS, x0[0] + y0[0], -dnt0));
    float e01 = __expf(fmaf(DS, x0[1] + y0[1], -dnt0));
    float e02 = __expf(fmaf(DS, x0[2] + y0[2], -dnt1));
    float e03 = __expf(fmaf(DS, x0[3] + y0[3], -dnt1));
    float e10 = __expf(fmaf(DS, x1[0] + y1[0], -dnt0));
    float e11 = __expf(fmaf(DS, x1[1] + y1[1], -dnt0));
    float e12 = __expf(fmaf(DS, x1[2] + y1[2], -dnt1));
    float e13 = __expf(fmaf(DS, x1[3] + y1[3], -dnt1));

    float2 kv0 = *(float2*)(ks_s + j0 + qd*2);
    float2 kv1 = *(float2*)(ks_s + j0 + 8 + qd*2);
    den0 = fmaf(e00, kv0.x, fmaf(e01, kv0.y, fmaf(e10, kv1.x, fmaf(e11, kv1.y, den0))));
    den1 = fmaf(e02, kv0.x, fmaf(e03, kv0.y, fmaf(e12, kv1.x, fmaf(e13, kv1.y, den1))));

    // accumulator -> A fragment (layout identity), bf16 hi/lo split
    __nv_bfloat16 h00 = __float2bfloat16(e00), h01 = __float2bfloat16(e01);
    __nv_bfloat16 h02 = __float2bfloat16(e02), h03 = __float2bfloat16(e03);
    __nv_bfloat16 h10 = __float2bfloat16(e10), h11 = __float2bfloat16(e11);
    __nv_bfloat16 h12 = __float2bfloat16(e12), h13 = __float2bfloat16(e13);
    uint32_t qa_hi[4] = { packb(h00, h01), packb(h02, h03),
                          packb(h10, h11), packb(h12, h13) };
    uint32_t qa_lo[4] = {
      packb(__float2bfloat16(e00 - __bfloat162float(h00)),
            __float2bfloat16(e01 - __bfloat162float(h01))),
      packb(__float2bfloat16(e02 - __bfloat162float(h02)),
            __float2bfloat16(e03 - __bfloat162float(h03))),
      packb(__float2bfloat16(e10 - __bfloat162float(h10)),
            __float2bfloat16(e11 - __bfloat162float(h11))),
      packb(__float2bfloat16(e12 - __bfloat162float(h12)),
            __float2bfloat16(e13 - __bfloat162float(h13))) };

    // MMA2: oacc[et] += qp @ ctx(k=j0..j0+15, n=et*8..et*8+7)
    const int ch0 = jt * 2;
    const uint32_t sw0 = (uint32_t)(((ch0 & 24) | ((ch0 ^ grp) & 7)) << 4);
    const uint32_t sw1 = (uint32_t)((((ch0+1) & 24) | (((ch0+1) ^ grp) & 7)) << 4);
#pragma unroll
    for (int et = 0; et < 8; et++) {
      uint32_t rb = (uint32_t)(et*8 + grp) * 512u + (uint32_t)(qd * 4);
      uint32_t bh2[2] = { *(uint32_t*)(smc + OCHI + rb + sw0),
                          *(uint32_t*)(smc + OCHI + rb + sw1) };
      uint32_t bl2[2] = { *(uint32_t*)(smc + OCLO + rb + sw0),
                          *(uint32_t*)(smc + OCLO + rb + sw1) };
      mma_bf16(oacc[et], qa_hi, bh2, oacc[et]);
      mma_bf16(oacc[et], qa_lo, bh2, oacc[et]);
      mma_bf16(oacc[et], qa_hi, bl2, oacc[et]);
    }
  }

  // finalize: denom butterfly over the quad, scale, store
  den0 += __shfl_xor_sync(0xffffffff, den0, 1);
  den0 += __shfl_xor_sync(0xffffffff, den0, 2);
  den1 += __shfl_xor_sync(0xffffffff, den1, 1);
  den1 += __shfl_xor_sync(0xffffffff, den1, 2);
  float inv0 = 1.f / den0, inv1 = 1.f / den1;

  float* og0 = outg + ((size_t)(bh * T_ + t0 + r0 + grp)) * DH_;
  float* og1 = og0 + 8 * DH_;
#pragma unroll
  for (int et = 0; et < 8; et++) {
    int col = et * 8 + qd * 2;
    *(float2*)(og0 + col) = make_float2(oacc[et][0] * inv0, oacc[et][1] * inv0);
    *(float2*)(og1 + col) = make_float2(oacc[et][2] * inv1, oacc[et][3] * inv1);
  }
}

// ---------------------------------------------------------------------------
extern "C" void kernel_launch(void* const* d_in, const int* in_sizes, int n_in,
                              void* d_out, int out_size) {
  const float* q    = (const float*)d_in[0];
  const float* k    = (const float*)d_in[1];
  const float* v    = (const float*)d_in[2];
  const float* proj = (const float*)d_in[3];
  float* out = (float*)d_out;

  const int smemA = (64*NF_ + 64*64 + 64 + 64 + 64*33) * 4;
  const int smemB = (64*NF_ + 64*64) * 4;
  const int smemC = SMEMC;

  cudaFuncSetAttribute(kernelA, cudaFuncAttributeMaxDynamicSharedMemorySize, smemA);
  cudaFuncSetAttribute(kernelB, cudaFuncAttributeMaxDynamicSharedMemorySize, smemB);
  cudaFuncSetAttribute(kernelC, cudaFuncAttributeMaxDynamicSharedMemorySize, smemC);

  zero_kernel<<<256, 256>>>();
  kernelA<<<dim3(T_/64, BH_), 256, smemA>>>(k, proj);
  kernelB<<<dim3(8, BH_), 256, smemB>>>(v);
  kernelC<<<dim3(T_/128, BH_), 256, smemC>>>(q, proj, out);
}

// round 12
// speedup vs baseline: 2.7305x; 1.6068x over previous
#include <cuda_runtime.h>
#include <cuda_bf16.h>
#include <math.h>
#include <cstdint>

#define T_  4096
#define NF_ 256
#define DH_ 64
#define BH_ 64
#define DS  0.35355339059327373f
#define DNC 0.0625f

// ctx+ksum scratch: [bh][e'=72][j=256], row 64 = ksum, rows 65-71 junk-zero
__device__ float g_ctx[BH_ * 72 * NF_];

__device__ __forceinline__ uint32_t packb(__nv_bfloat16 a, __nv_bfloat16 b) {
  __nv_bfloat162 t(a, b);
  return *reinterpret_cast<uint32_t*>(&t);
}

__device__ __forceinline__ void cvt_hilo(float4 v, uint2& hi, uint2& lo) {
  __nv_bfloat16 h0 = __float2bfloat16(v.x), h1 = __float2bfloat16(v.y);
  __nv_bfloat16 h2 = __float2bfloat16(v.z), h3 = __float2bfloat16(v.w);
  hi = make_uint2(packb(h0, h1), packb(h2, h3));
  lo = make_uint2(packb(__float2bfloat16(v.x - __bfloat162float(h0)),
                        __float2bfloat16(v.y - __bfloat162float(h1))),
                  packb(__float2bfloat16(v.z - __bfloat162float(h2)),
                        __float2bfloat16(v.w - __bfloat162float(h3))));
}

// m16n8k16 row.col bf16 -> f32
__device__ __forceinline__ void mma_bf16(float* d, const uint32_t* a,
                                         const uint32_t* b, const float* c) {
  asm volatile(
      "mma.sync.aligned.m16n8k16.row.col.f32.bf16.bf16.f32 "
      "{%0,%1,%2,%3}, {%4,%5,%6,%7}, {%8,%9}, {%10,%11,%12,%13};"
      : "=f"(d[0]), "=f"(d[1]), "=f"(d[2]), "=f"(d[3])
      : "r"(a[0]), "r"(a[1]), "r"(a[2]), "r"(a[3]),
        "r"(b[0]), "r"(b[1]),
        "f"(c[0]), "f"(c[1]), "f"(c[2]), "f"(c[3]));
}

__device__ __forceinline__ void sth(void* p, float v) {
  __nv_bfloat16 h = __float2bfloat16(v);
  *(__nv_bfloat16*)p = h;
}
__device__ __forceinline__ void sth_lo(void* p, float v) {
  __nv_bfloat16 h = __float2bfloat16(v);
  *(__nv_bfloat16*)p = __float2bfloat16(v - __bfloat162float(h));
}

// ---------------------------------------------------------------------------
__global__ void zero_kernel() {
  int idx = blockIdx.x * blockDim.x + threadIdx.x;
  const int n = BH_ * 72 * NF_;
  for (int i = idx; i < n; i += gridDim.x * blockDim.x) g_ctx[i] = 0.f;
}

// ---------------------------------------------------------------------------
// Fused kernel AB: per block (8 x 64 grid): 512 tokens of one bh.
#define AB_OPHI 0
#define AB_OPLO 32768
#define AB_OKHI 65536
#define AB_OKLO 73728
#define AB_OSHI 81920
#define AB_OSLO 114688
#define AB_OVHI 147456
#define AB_OVLO 156672
#define AB_OW   165888
#define AB_ODN  166144
#define AB_OMX  166400
#define SMEMAB  166912

__global__ __launch_bounds__(256, 1)
void kernelAB(const float* __restrict__ kin,
              const float* __restrict__ vin,
              const float* __restrict__ proj) {
  extern __shared__ char smc[];
  float* w_s  = (float*)(smc + AB_OW);
  float* dn_s = (float*)(smc + AB_ODN);
  float* mx_s = (float*)(smc + AB_OMX);

  const int tid  = threadIdx.x;
  const int warp = tid >> 5;
  const int lane = tid & 31;
  const int grp  = lane >> 2;
  const int qd   = lane & 3;
  const int bh   = blockIdx.y;
  const int tb   = blockIdx.x * 512;

  // --- proj [256][64] -> bf16 hi/lo, 128B swizzled rows (once per block) ---
  {
    const float4* pg = (const float4*)proj;
#pragma unroll
    for (int it = 0; it < 16; it++) {
      int i = tid + it * 256;
      int row = i >> 4, kp = (i & 15) * 4;
      uint32_t off = (uint32_t)row*128 + (uint32_t)(((kp>>3) ^ (row&7)) << 4)
                   + (uint32_t)((kp&7)*2);
      uint2 hi, lo; cvt_hilo(pg[i], hi, lo);
      *(uint2*)(smc + AB_OPHI + off) = hi;
      *(uint2*)(smc + AB_OPLO + off) = lo;
    }
  }
  // --- zero v' rows 65..71 (hi and lo) ---
  for (int i = tid; i < 448; i += 256) {
    *(uint16_t*)(smc + AB_OVHI + 65*128 + i*2) = 0;
    *(uint16_t*)(smc + AB_OVLO + 65*128 + i*2) = 0;
  }

  float oacc[2][9][4];
#pragma unroll
  for (int a = 0; a < 2; a++)
#pragma unroll
    for (int b = 0; b < 9; b++)
#pragma unroll
      for (int c = 0; c < 4; c++) oacc[a][b][c] = 0.f;

  const int mt = warp >> 1;      // MMA1 m-tile (token rows mt*16..)
  const int nh = warp & 1;       // MMA1 j-half (nh*128..)
  const int r0 = mt * 16;
  const int rq  = tid >> 2;      // loader row (0..63)
  const int qtr = tid & 3;       // loader quarter

  for (int it = 0; it < 8; it++) {
    const int t0 = tb + it * 64;
    __syncthreads();   // protect smem tiles from previous subtile readers

    // --- phase 1: load k subtile -> k_s hi/lo + dn ---
    {
      const float4* kg = (const float4*)(kin + ((size_t)(bh*T_ + t0 + rq)) * DH_);
      float dsum = 0.f;
#pragma unroll
      for (int c = 0; c < 4; c++) {
        float4 v = kg[qtr*4 + c];
        dsum += v.x*v.x + v.y*v.y + v.z*v.z + v.w*v.w;
        int g4 = qtr*4 + c;
        uint32_t off = (uint32_t)rq*128
                     + (uint32_t)((((g4>>1) ^ (rq&7)) << 4)) + (uint32_t)((g4&1)*8);
        uint2 hi, lo; cvt_hilo(v, hi, lo);
        *(uint2*)(smc + AB_OKHI + off) = hi;
        *(uint2*)(smc + AB_OKLO + off) = lo;
      }
      dsum += __shfl_xor_sync(0xffffffff, dsum, 1);
      dsum += __shfl_xor_sync(0xffffffff, dsum, 2);
      if (qtr == 0) dn_s[rq] = dsum;
    }
    __syncthreads();

    // --- phase 2: MMA1 + exp + transposed scatter + rowmax ---
    {
      uint32_t aq_hi[4][4], aq_lo[4][4];
#pragma unroll
      for (int kc = 0; kc < 4; kc++) {
        uint32_t c0 = (uint32_t)(((kc*2)     ^ grp) << 4);
        uint32_t c1 = (uint32_t)(((kc*2 + 1) ^ grp) << 4);
        uint32_t b0 = (uint32_t)(r0 + grp)     * 128u + (uint32_t)(qd * 4);
        uint32_t b1 = (uint32_t)(r0 + grp + 8) * 128u + (uint32_t)(qd * 4);
        aq_hi[kc][0] = *(uint32_t*)(smc + AB_OKHI + b0 + c0);
        aq_hi[kc][1] = *(uint32_t*)(smc + AB_OKHI + b1 + c0);
        aq_hi[kc][2] = *(uint32_t*)(smc + AB_OKHI + b0 + c1);
        aq_hi[kc][3] = *(uint32_t*)(smc + AB_OKHI + b1 + c1);
        aq_lo[kc][0] = *(uint32_t*)(smc + AB_OKLO + b0 + c0);
        aq_lo[kc][1] = *(uint32_t*)(smc + AB_OKLO + b1 + c0);
        aq_lo[kc][2] = *(uint32_t*)(smc + AB_OKLO + b0 + c1);
        aq_lo[kc][3] = *(uint32_t*)(smc + AB_OKLO + b1 + c1);
      }
      const float dnt0 = DNC * dn_s[r0 + grp];
      const float dnt1 = DNC * dn_s[r0 + grp + 8];
      const int ta  = r0 + grp;
      const int tbq = r0 + grp + 8;
      float mm0 = -1e30f, mm1 = -1e30f;

      for (int jt8 = 0; jt8 < 8; jt8++) {
        const int j0 = nh * 128 + jt8 * 16;
        float x0[4] = {0,0,0,0}, y0[4] = {0,0,0,0};
        float x1[4] = {0,0,0,0}, y1[4] = {0,0,0,0};
#pragma unroll
        for (int kc = 0; kc < 4; kc++) {
          uint32_t c0 = (uint32_t)(((kc*2)     ^ grp) << 4);
          uint32_t c1 = (uint32_t)(((kc*2 + 1) ^ grp) << 4);
          uint32_t rb0 = (uint32_t)(j0 + grp)     * 128u + (uint32_t)(qd * 4);
          uint32_t rb1 = (uint32_t)(j0 + 8 + grp) * 128u + (uint32_t)(qd * 4);
          uint32_t b0h[2] = { *(uint32_t*)(smc + AB_OPHI + rb0 + c0),
                              *(uint32_t*)(smc + AB_OPHI + rb0 + c1) };
          uint32_t b0l[2] = { *(uint32_t*)(smc + AB_OPLO + rb0 + c0),
                              *(uint32_t*)(smc + AB_OPLO + rb0 + c1) };
          uint32_t b1h[2] = { *(uint32_t*)(smc + AB_OPHI + rb1 + c0),
                              *(uint32_t*)(smc + AB_OPHI + rb1 + c1) };
          uint32_t b1l[2] = { *(uint32_t*)(smc + AB_OPLO + rb1 + c0),
                              *(uint32_t*)(smc + AB_OPLO + rb1 + c1) };
          mma_bf16(x0, aq_hi[kc], b0h, x0);
          mma_bf16(y0, aq_lo[kc], b0h, y0);
          mma_bf16(y0, aq_hi[kc], b0l, y0);
          mma_bf16(x1, aq_hi[kc], b1h, x1);
          mma_bf16(y1, aq_lo[kc], b1h, y1);
          mma_bf16(y1, aq_hi[kc], b1l, y1);
        }
        float d00 = DS*(x0[0]+y0[0]), d01 = DS*(x0[1]+y0[1]);
        float d02 = DS*(x0[2]+y0[2]), d03 = DS*(x0[3]+y0[3]);
        float d10 = DS*(x1[0]+y1[0]), d11 = DS*(x1[1]+y1[1]);
        float d12 = DS*(x1[2]+y1[2]), d13 = DS*(x1[3]+y1[3]);
        mm0 = fmaxf(mm0, fmaxf(fmaxf(d00, d01), fmaxf(d10, d11)));
        mm1 = fmaxf(mm1, fmaxf(fmaxf(d02, d03), fmaxf(d12, d13)));
        float e00 = __expf(d00 - dnt0), e01 = __expf(d01 - dnt0);
        float e02 = __expf(d02 - dnt1), e03 = __expf(d03 - dnt1);
        float e10 = __expf(d10 - dnt0), e11 = __expf(d11 - dnt0);
        float e12 = __expf(d12 - dnt1), e13 = __expf(d13 - dnt1);

        // transposed scatter: sT[j][t]
        const int ja = j0 + qd*2;
#pragma unroll
        for (int u = 0; u < 2; u++) {
          int j_0 = ja + u*8, j_1 = ja + u*8 + 1;
          float va0 = u ? e10 : e00, vb0 = u ? e11 : e01;
          float va1 = u ? e12 : e02, vb1 = u ? e13 : e03;
          uint32_t a00 = (uint32_t)j_0*128 + ((((ta >>3) ^ (j_0&7))<<4)) + (ta &7)*2;
          uint32_t a01 = (uint32_t)j_1*128 + ((((ta >>3) ^ (j_1&7))<<4)) + (ta &7)*2;
          uint32_t a10 = (uint32_t)j_0*128 + ((((tbq>>3) ^ (j_0&7))<<4)) + (tbq&7)*2;
          uint32_t a11 = (uint32_t)j_1*128 + ((((tbq>>3) ^ (j_1&7))<<4)) + (tbq&7)*2;
          sth(smc + AB_OSHI + a00, va0);  sth_lo(smc + AB_OSLO + a00, va0);
          sth(smc + AB_OSHI + a01, vb0);  sth_lo(smc + AB_OSLO + a01, vb0);
          sth(smc + AB_OSHI + a10, va1);  sth_lo(smc + AB_OSLO + a10, va1);
          sth(smc + AB_OSHI + a11, vb1);  sth_lo(smc + AB_OSLO + a11, vb1);
        }
      }
      mm0 = fmaxf(mm0, __shfl_xor_sync(0xffffffff, mm0, 1));
      mm0 = fmaxf(mm0, __shfl_xor_sync(0xffffffff, mm0, 2));
      mm1 = fmaxf(mm1, __shfl_xor_sync(0xffffffff, mm1, 1));
      mm1 = fmaxf(mm1, __shfl_xor_sync(0xffffffff, mm1, 2));
      if (qd == 0) {
        mx_s[(r0 + grp) * 2 + nh]     = mm0;
        mx_s[(r0 + grp + 8) * 2 + nh] = mm1;
      }
    }
    __syncthreads();

    // --- phase 3: w = exp(-rowmax) ---
    if (tid < 64) w_s[tid] = __expf(-fmaxf(mx_s[tid*2], mx_s[tid*2+1]));
    __syncthreads();

    // --- phase 4: v' = w*v transposed to vT[e][t]; w column at e=64 ---
    {
      const float4* vg = (const float4*)(vin + ((size_t)(bh*T_ + t0 + rq)) * DH_);
      float w = w_s[rq];
#pragma unroll
      for (int c = 0; c < 4; c++) {
        float4 v = vg[qtr*4 + c];
        v.x *= w; v.y *= w; v.z *= w; v.w *= w;
        int e0 = qtr*16 + c*4;
        float vv[4] = {v.x, v.y, v.z, v.w};
#pragma unroll
        for (int l = 0; l < 4; l++) {
          int e = e0 + l;
          uint32_t off = (uint32_t)e*128 + ((((rq>>3) ^ (e&7))<<4)) + (rq&7)*2;
          sth(smc + AB_OVHI + off, vv[l]);
          sth_lo(smc + AB_OVLO + off, vv[l]);
        }
      }
      if (tid < 64) {
        float w2 = w_s[tid];
        uint32_t off = (uint32_t)64*128 + (((tid>>3))<<4) + (tid&7)*2;
        sth(smc + AB_OVHI + off, w2);
        sth_lo(smc + AB_OVLO + off, w2);
      }
    }
    __syncthreads();

    // --- phase 5: MMA2: oacc += sT @ v'  (kc outer to cap register pressure) ---
#pragma unroll
    for (int mt2 = 0; mt2 < 2; mt2++) {
      const int jm = warp * 32 + mt2 * 16;
#pragma unroll
      for (int kc = 0; kc < 4; kc++) {
        uint32_t c0 = (uint32_t)(((kc*2)     ^ grp) << 4);
        uint32_t c1 = (uint32_t)(((kc*2 + 1) ^ grp) << 4);
        uint32_t b0 = (uint32_t)(jm + grp)     * 128u + (uint32_t)(qd * 4);
        uint32_t b1 = (uint32_t)(jm + grp + 8) * 128u + (uint32_t)(qd * 4);
        uint32_t as_hi[4], as_lo[4];
        as_hi[0] = *(uint32_t*)(smc + AB_OSHI + b0 + c0);
        as_hi[1] = *(uint32_t*)(smc + AB_OSHI + b1 + c0);
        as_hi[2] = *(uint32_t*)(smc + AB_OSHI + b0 + c1);
        as_hi[3] = *(uint32_t*)(smc + AB_OSHI + b1 + c1);
        as_lo[0] = *(uint32_t*)(smc + AB_OSLO + b0 + c0);
        as_lo[1] = *(uint32_t*)(smc + AB_OSLO + b1 + c0);
        as_lo[2] = *(uint32_t*)(smc + AB_OSLO + b0 + c1);
        as_lo[3] = *(uint32_t*)(smc + AB_OSLO + b1 + c1);
#pragma unroll
        for (int nt = 0; nt < 9; nt++) {
          uint32_t rb = (uint32_t)(nt*8 + grp) * 128u + (uint32_t)(qd * 4);
          uint32_t bvh[2] = { *(uint32_t*)(smc + AB_OVHI + rb + c0),
                              *(uint32_t*)(smc + AB_OVHI + rb + c1) };
          uint32_t bvl[2] = { *(uint32_t*)(smc + AB_OVLO + rb + c0),
                              *(uint32_t*)(smc + AB_OVLO + rb + c1) };
          mma_bf16(oacc[mt2][nt], as_hi, bvh, oacc[mt2][nt]);
          mma_bf16(oacc[mt2][nt], as_lo, bvh, oacc[mt2][nt]);
          mma_bf16(oacc[mt2][nt], as_hi, bvl, oacc[mt2][nt]);
        }
      }
    }
  }

  // --- final: atomic reduce into g_ctx[bh][e'][j] ---
  float* ctx = g_ctx + bh * 72 * NF_;
#pragma unroll
  for (int mt2 = 0; mt2 < 2; mt2++)
#pragma unroll
    for (int nt = 0; nt < 9; nt++)
#pragma unroll
      for (int c = 0; c < 4; c++) {
        int j = warp*32 + mt2*16 + grp + ((c >= 2) ? 8 : 0);
        int e = nt*8 + qd*2 + (c & 1);
        if (e < 65) atomicAdd(&ctx[e * NF_ + j], oacc[mt2][nt][c]);
      }
}

// ---------------------------------------------------------------------------
// Kernel C (unchanged from R9 except ctx/ksum come from g_ctx[bh][72][256])
#define OQHI  0
#define OQLO  16384
#define OPHI  32768
#define OPLO  65536
#define OCHI  98304
#define OCLO  131072
#define OKS   163840
#define ODN   164864
#define SMEMC 165504

__global__ __launch_bounds__(256, 1)
void kernelC(const float* __restrict__ qin,
             const float* __restrict__ proj,
             float* __restrict__ outg) {
  extern __shared__ char smc[];
  float* ks_s = (float*)(smc + OKS);
  float* dn_s = (float*)(smc + ODN);

  const int tid  = threadIdx.x;
  const int warp = tid >> 5;
  const int lane = tid & 31;
  const int grp  = lane >> 2;
  const int qd   = lane & 3;
  const int bh   = blockIdx.y;
  const int t0   = blockIdx.x * 128;

  {
    const float4* pg = (const float4*)proj;
#pragma unroll
    for (int it = 0; it < 16; it++) {
      int i = tid + it * 256;
      int row = i >> 4, kp = (i & 15) * 4;
      uint32_t off = (uint32_t)row*128 + (uint32_t)(((kp>>3) ^ (row&7)) << 4)
                   + (uint32_t)((kp&7)*2);
      uint2 hi, lo; cvt_hilo(pg[i], hi, lo);
      *(uint2*)(smc + OPHI + off) = hi;
      *(uint2*)(smc + OPLO + off) = lo;
    }
  }
  {
    const float4* cg = (const float4*)(g_ctx + bh * 72 * NF_);
#pragma unroll
    for (int it = 0; it < 16; it++) {
      int i = tid + it * 256;
      int e = i >> 6, j4 = (i & 63) * 4;
      int ch = j4 >> 3;
      int swc = (ch & 24) | ((ch ^ e) & 7);
      uint32_t off = (uint32_t)e*512 + (uint32_t)(swc << 4) + (uint32_t)((j4&7)*2);
      uint2 hi, lo; cvt_hilo(cg[i], hi, lo);
      *(uint2*)(smc + OCHI + off) = hi;
      *(uint2*)(smc + OCLO + off) = lo;
    }
  }
  {
    const int rq = tid >> 1, half = tid & 1;
    const float4* qg = (const float4*)(qin + ((size_t)(bh * T_ + t0 + rq)) * DH_);
    float dsum = 0.f;
#pragma unroll
    for (int c = 0; c < 8; c++) {
      float4 v = qg[half*8 + c];
      dsum += v.x*v.x + v.y*v.y + v.z*v.z + v.w*v.w;
      int kp = half*32 + c*4;
      uint32_t off = (uint32_t)rq*128 + (uint32_t)(((kp>>3) ^ (rq&7)) << 4)
                   + (uint32_t)((kp&7)*2);
      uint2 hi, lo; cvt_hilo(v, hi, lo);
      *(uint2*)(smc + OQHI + off) = hi;
      *(uint2*)(smc + OQLO + off) = lo;
    }
    dsum += __shfl_xor_sync(0xffffffff, dsum, 1);
    if (half == 0) dn_s[rq] = dsum;
  }
  ks_s[tid] = g_ctx[bh * 72 * NF_ + 64 * NF_ + tid];
  __syncthreads();

  const int r0 = warp * 16;
  uint32_t aq_hi[4][4], aq_lo[4][4];
#pragma unroll
  for (int kc = 0; kc < 4; kc++) {
    uint32_t c0 = (uint32_t)(((kc*2)     ^ grp) << 4);
    uint32_t c1 = (uint32_t)(((kc*2 + 1) ^ grp) << 4);
    uint32_t base0 = (uint32_t)(r0 + grp)     * 128u + (uint32_t)(qd * 4);
    uint32_t base1 = (uint32_t)(r0 + grp + 8) * 128u + (uint32_t)(qd * 4);
    aq_hi[kc][0] = *(uint32_t*)(smc + OQHI + base0 + c0);
    aq_hi[kc][1] = *(uint32_t*)(smc + OQHI + base1 + c0);
    aq_hi[kc][2] = *(uint32_t*)(smc + OQHI + base0 + c1);
    aq_hi[kc][3] = *(uint32_t*)(smc + OQHI + base1 + c1);
    aq_lo[kc][0] = *(uint32_t*)(smc + OQLO + base0 + c0);
    aq_lo[kc][1] = *(uint32_t*)(smc + OQLO + base1 + c0);
    aq_lo[kc][2] = *(uint32_t*)(smc + OQLO + base0 + c1);
    aq_lo[kc][3] = *(uint32_t*)(smc + OQLO + base1 + c1);
  }

  float oacc[8][4];
#pragma unroll
  for (int et = 0; et < 8; et++)
#pragma unroll
    for (int i = 0; i < 4; i++) oacc[et][i] = 0.f;

  float den0 = 0.f, den1 = 0.f;
  const float dnt0 = DNC * dn_s[r0 + grp];
  const float dnt1 = DNC * dn_s[r0 + grp + 8];

  for (int jt = 0; jt < 16; jt++) {
    const int j0 = jt * 16;
    float x0[4] = {0,0,0,0}, y0[4] = {0,0,0,0};
    float x1[4] = {0,0,0,0}, y1[4] = {0,0,0,0};
#pragma unroll
    for (int kc = 0; kc < 4; kc++) {
      uint32_t c0 = (uint32_t)(((kc*2)     ^ grp) << 4);
      uint32_t c1 = (uint32_t)(((kc*2 + 1) ^ grp) << 4);
      uint32_t rb0 = (uint32_t)(j0 + grp)     * 128u + (uint32_t)(qd * 4);
      uint32_t rb1 = (uint32_t)(j0 + 8 + grp) * 128u + (uint32_t)(qd * 4);
      uint32_t b0h[2] = { *(uint32_t*)(smc + OPHI + rb0 + c0),
                          *(uint32_t*)(smc + OPHI + rb0 + c1) };
      uint32_t b0l[2] = { *(uint32_t*)(smc + OPLO + rb0 + c0),
                          *(uint32_t*)(smc + OPLO + rb0 + c1) };
      uint32_t b1h[2] = { *(uint32_t*)(smc + OPHI + rb1 + c0),
                          *(uint32_t*)(smc + OPHI + rb1 + c1) };
      uint32_t b1l[2] = { *(uint32_t*)(smc + OPLO + rb1 + c0),
                          *(uint32_t*)(smc + OPLO + rb1 + c1) };
      mma_bf16(x0, aq_hi[kc], b0h, x0);
      mma_bf16(y0, aq_lo[kc], b0h, y0);
      mma_bf16(y0, aq_hi[kc], b0l, y0);
      mma_bf16(x1, aq_hi[kc], b1h, x1);
      mma_bf16(y1, aq_lo[kc], b1h, y1);
      mma_bf16(y1, aq_hi[kc], b1l, y1);
    }

    float e00 = __expf(fmaf(DS, x0[0] + y0[0], -dnt0));
    float e01 = __expf(fmaf(DS, x0[1] + y0[1], -dnt0));
    float e02 = __expf(fmaf(DS, x0[2] + y0[2], -dnt1));
    float e03 = __expf(fmaf(DS, x0[3] + y0[3], -dnt1));
    float e10 = __expf(fmaf(DS, x1[0] + y1[0], -dnt0));
    float e11 = __expf(fmaf(DS, x1[1] + y1[1], -dnt0));
    float e12 = __expf(fmaf(DS, x1[2] + y1[2], -dnt1));
    float e13 = __expf(fmaf(DS, x1[3] + y1[3], -dnt1));

    float2 kv0 = *(float2*)(ks_s + j0 + qd*2);
    float2 kv1 = *(float2*)(ks_s + j0 + 8 + qd*2);
    den0 = fmaf(e00, kv0.x, fmaf(e01, kv0.y, fmaf(e10, kv1.x, fmaf(e11, kv1.y, den0))));
    den1 = fmaf(e02, kv0.x, fmaf(e03, kv0.y, fmaf(e12, kv1.x, fmaf(e13, kv1.y, den1))));

    __nv_bfloat16 h00 = __float2bfloat16(e00), h01 = __float2bfloat16(e01);
    __nv_bfloat16 h02 = __float2bfloat16(e02), h03 = __float2bfloat16(e03);
    __nv_bfloat16 h10 = __float2bfloat16(e10), h11 = __float2bfloat16(e11);
    __nv_bfloat16 h12 = __float2bfloat16(e12), h13 = __float2bfloat16(e13);
    uint32_t qa_hi[4] = { packb(h00, h01), packb(h02, h03),
                          packb(h10, h11), packb(h12, h13) };
    uint32_t qa_lo[4] = {
      packb(__float2bfloat16(e00 - __bfloat162float(h00)),
            __float2bfloat16(e01 - __bfloat162float(h01))),
      packb(__float2bfloat16(e02 - __bfloat162float(h02)),
            __float2bfloat16(e03 - __bfloat162float(h03))),
      packb(__float2bfloat16(e10 - __bfloat162float(h10)),
            __float2bfloat16(e11 - __bfloat162float(h11))),
      packb(__float2bfloat16(e12 - __bfloat162float(h12)),
            __float2bfloat16(e13 - __bfloat162float(h13))) };

    const int ch0 = jt * 2;
    const uint32_t sw0 = (uint32_t)(((ch0 & 24) | ((ch0 ^ grp) & 7)) << 4);
    const uint32_t sw1 = (uint32_t)((((ch0+1) & 24) | (((ch0+1) ^ grp) & 7)) << 4);
#pragma unroll
    for (int et = 0; et < 8; et++) {
      uint32_t rb = (uint32_t)(et*8 + grp) * 512u + (uint32_t)(qd * 4);
      uint32_t bh2[2] = { *(uint32_t*)(smc + OCHI + rb + sw0),
                          *(uint32_t*)(smc + OCHI + rb + sw1) };
      uint32_t bl2[2] = { *(uint32_t*)(smc + OCLO + rb + sw0),
                          *(uint32_t*)(smc + OCLO + rb + sw1) };
      mma_bf16(oacc[et], qa_hi, bh2, oacc[et]);
      mma_bf16(oacc[et], qa_lo, bh2, oacc[et]);
      mma_bf16(oacc[et], qa_hi, bl2, oacc[et]);
    }
  }

  den0 += __shfl_xor_sync(0xffffffff, den0, 1);
  den0 += __shfl_xor_sync(0xffffffff, den0, 2);
  den1 += __shfl_xor_sync(0xffffffff, den1, 1);
  den1 += __shfl_xor_sync(0xffffffff, den1, 2);
  float inv0 = 1.f / den0, inv1 = 1.f / den1;

  float* og0 = outg + ((size_t)(bh * T_ + t0 + r0 + grp)) * DH_;
  float* og1 = og0 + 8 * DH_;
#pragma unroll
  for (int et = 0; et < 8; et++) {
    int col = et * 8 + qd * 2;
    *(float2*)(og0 + col) = make_float2(oacc[et][0] * inv0, oacc[et][1] * inv0);
    *(float2*)(og1 + col) = make_float2(oacc[et][2] * inv1, oacc[et][3] * inv1);
  }
}

// ---------------------------------------------------------------------------
extern "C" void kernel_launch(void* const* d_in, const int* in_sizes, int n_in,
                              void* d_out, int out_size) {
  const float* q    = (const float*)d_in[0];
  const float* k    = (const float*)d_in[1];
  const float* v    = (const float*)d_in[2];
  const float* proj = (const float*)d_in[3];
  float* out = (float*)d_out;

  cudaFuncSetAttribute(kernelAB, cudaFuncAttributeMaxDynamicSharedMemorySize, SMEMAB);
  cudaFuncSetAttribute(kernelC,  cudaFuncAttributeMaxDynamicSharedMemorySize, SMEMC);

  zero_kernel<<<256, 256>>>();
  kernelAB<<<dim3(8, BH_), 256, SMEMAB>>>(k, v, proj);
  kernelC<<<dim3(T_/128, BH_), 256, SMEMC>>>(q, proj, out);
}

// round 13
// speedup vs baseline: 2.8591x; 1.0471x over previous
#include <cuda_runtime.h>
#include <cuda_bf16.h>
#include <math.h>
#include <cstdint>

#define T_  4096
#define NF_ 256
#define DH_ 64
#define BH_ 64
#define DS  0.35355339059327373f
#define DNC 0.0625f

// per-xb partial ctx: [xb=8][bh][e'=72][j=256] (only e<65 written/read)
__device__ float g_ctx_part[8 * BH_ * 72 * NF_];
// reduced ctx+ksum: [bh][e'=72][j=256], row 64 = ksum
__device__ float g_ctx[BH_ * 72 * NF_];

__device__ __forceinline__ uint32_t smem_u32(const void* p) {
  uint32_t a;
  asm("{ .reg .u64 tmp; cvta.to.shared.u64 tmp, %1; cvt.u32.u64 %0, tmp; }"
      : "=r"(a) : "l"(p));
  return a;
}

__device__ __forceinline__ void ldmx4(uint32_t* r, uint32_t addr) {
  asm volatile("ldmatrix.sync.aligned.m8n8.x4.shared.b16 {%0,%1,%2,%3}, [%4];"
      : "=r"(r[0]), "=r"(r[1]), "=r"(r[2]), "=r"(r[3]) : "r"(addr));
}

__device__ __forceinline__ uint32_t packb(__nv_bfloat16 a, __nv_bfloat16 b) {
  __nv_bfloat162 t(a, b);
  return *reinterpret_cast<uint32_t*>(&t);
}

__device__ __forceinline__ void cvt_hilo(float4 v, uint2& hi, uint2& lo) {
  __nv_bfloat16 h0 = __float2bfloat16(v.x), h1 = __float2bfloat16(v.y);
  __nv_bfloat16 h2 = __float2bfloat16(v.z), h3 = __float2bfloat16(v.w);
  hi = make_uint2(packb(h0, h1), packb(h2, h3));
  lo = make_uint2(packb(__float2bfloat16(v.x - __bfloat162float(h0)),
                        __float2bfloat16(v.y - __bfloat162float(h1))),
                  packb(__float2bfloat16(v.z - __bfloat162float(h2)),
                        __float2bfloat16(v.w - __bfloat162float(h3))));
}

// m16n8k16 row.col bf16 -> f32
__device__ __forceinline__ void mma_bf16(float* d, const uint32_t* a,
                                         const uint32_t* b, const float* c) {
  asm volatile(
      "mma.sync.aligned.m16n8k16.row.col.f32.bf16.bf16.f32 "
      "{%0,%1,%2,%3}, {%4,%5,%6,%7}, {%8,%9}, {%10,%11,%12,%13};"
      : "=f"(d[0]), "=f"(d[1]), "=f"(d[2]), "=f"(d[3])
      : "r"(a[0]), "r"(a[1]), "r"(a[2]), "r"(a[3]),
        "r"(b[0]), "r"(b[1]),
        "f"(c[0]), "f"(c[1]), "f"(c[2]), "f"(c[3]));
}

__device__ __forceinline__ void sth(void* p, float v) {
  __nv_bfloat16 h = __float2bfloat16(v);
  *(__nv_bfloat16*)p = h;
}
__device__ __forceinline__ void sth_lo(void* p, float v) {
  __nv_bfloat16 h = __float2bfloat16(v);
  *(__nv_bfloat16*)p = __float2bfloat16(v - __bfloat162float(h));
}

// ---------------------------------------------------------------------------
// Reduce 8 partials -> g_ctx (covers e 0..64; rows 65-71 never read)
__global__ void reduce_kernel() {
  int idx = blockIdx.x * blockDim.x + threadIdx.x;
  const int n = BH_ * 65 * NF_;
  if (idx >= n) return;
  int bh = idx / (65 * NF_);
  int rem = idx % (65 * NF_);
  const size_t stride = (size_t)BH_ * 72 * NF_;
  const float* p = g_ctx_part + (size_t)bh * 72 * NF_ + rem;
  float s = 0.f;
#pragma unroll
  for (int xb = 0; xb < 8; xb++) s += p[xb * stride];
  g_ctx[bh * 72 * NF_ + rem] = s;
}

// ---------------------------------------------------------------------------
// Fused kernel AB: per block (8 x 64 grid): 512 tokens of one bh.
#define AB_OPHI 0
#define AB_OPLO 32768
#define AB_OKHI 65536
#define AB_OKLO 73728
#define AB_OSHI 81920
#define AB_OSLO 114688
#define AB_OVHI 147456
#define AB_OVLO 156672
#define AB_OW   165888
#define AB_ODN  166144
#define AB_OMX  166400
#define SMEMAB  166912

__global__ __launch_bounds__(256, 1)
void kernelAB(const float* __restrict__ kin,
              const float* __restrict__ vin,
              const float* __restrict__ proj) {
  extern __shared__ char smc[];
  const uint32_t sb = smem_u32(smc);
  float* w_s  = (float*)(smc + AB_OW);
  float* dn_s = (float*)(smc + AB_ODN);
  float* mx_s = (float*)(smc + AB_OMX);

  const int tid  = threadIdx.x;
  const int warp = tid >> 5;
  const int lane = tid & 31;
  const int grp  = lane >> 2;
  const int qd   = lane & 3;
  const int lg   = lane >> 3;    // ldmatrix address group 0..3
  const int li   = lane & 7;     // ldmatrix row within group
  const int bh   = blockIdx.y;
  const int tb   = blockIdx.x * 512;

  // --- proj [256][64] -> bf16 hi/lo, 128B swizzled rows ---
  {
    const float4* pg = (const float4*)proj;
#pragma unroll
    for (int it = 0; it < 16; it++) {
      int i = tid + it * 256;
      int row = i >> 4, kp = (i & 15) * 4;
      uint32_t off = (uint32_t)row*128 + (uint32_t)(((kp>>3) ^ (row&7)) << 4)
                   + (uint32_t)((kp&7)*2);
      uint2 hi, lo; cvt_hilo(pg[i], hi, lo);
      *(uint2*)(smc + AB_OPHI + off) = hi;
      *(uint2*)(smc + AB_OPLO + off) = lo;
    }
  }
  // --- zero v' rows 65..71 (hi and lo) ---
  for (int i = tid; i < 448; i += 256) {
    *(uint16_t*)(smc + AB_OVHI + 65*128 + i*2) = 0;
    *(uint16_t*)(smc + AB_OVLO + 65*128 + i*2) = 0;
  }

  float oacc[2][9][4];
#pragma unroll
  for (int a = 0; a < 2; a++)
#pragma unroll
    for (int b = 0; b < 9; b++)
#pragma unroll
      for (int c = 0; c < 4; c++) oacc[a][b][c] = 0.f;

  const int mt = warp >> 1;
  const int nh = warp & 1;
  const int r0 = mt * 16;
  const int rq  = tid >> 2;
  const int qtr = tid & 3;

  for (int it = 0; it < 8; it++) {
    const int t0 = tb + it * 64;
    __syncthreads();

    // --- phase 1: load k subtile -> k_s hi/lo + dn ---
    {
      const float4* kg = (const float4*)(kin + ((size_t)(bh*T_ + t0 + rq)) * DH_);
      float dsum = 0.f;
#pragma unroll
      for (int c = 0; c < 4; c++) {
        float4 v = kg[qtr*4 + c];
        dsum += v.x*v.x + v.y*v.y + v.z*v.z + v.w*v.w;
        int g4 = qtr*4 + c;
        uint32_t off = (uint32_t)rq*128
                     + (uint32_t)((((g4>>1) ^ (rq&7)) << 4)) + (uint32_t)((g4&1)*8);
        uint2 hi, lo; cvt_hilo(v, hi, lo);
        *(uint2*)(smc + AB_OKHI + off) = hi;
        *(uint2*)(smc + AB_OKLO + off) = lo;
      }
      dsum += __shfl_xor_sync(0xffffffff, dsum, 1);
      dsum += __shfl_xor_sync(0xffffffff, dsum, 2);
      if (qtr == 0) dn_s[rq] = dsum;
    }
    __syncthreads();

    // --- phase 2: MMA1 + exp + transposed scatter + rowmax ---
    {
      uint32_t aq_hi[4][4], aq_lo[4][4];
#pragma unroll
      for (int kc = 0; kc < 4; kc++) {
        // A tiles order: (m0,c0),(m8,c0),(m0,c1),(m8,c1)
        int row = r0 + ((lg & 1) << 3) + li;
        int ch  = kc*2 + (lg >> 1);
        uint32_t off = (uint32_t)row*128 + (uint32_t)(((ch ^ li) & 7) << 4)
                     + (uint32_t)((ch & 24) << 4);   // ch<8 here, high bits 0
        ldmx4(aq_hi[kc], sb + AB_OKHI + off);
        ldmx4(aq_lo[kc], sb + AB_OKLO + off);
      }
      const float dnt0 = DNC * dn_s[r0 + grp];
      const float dnt1 = DNC * dn_s[r0 + grp + 8];
      const int ta  = r0 + grp;
      const int tbq = r0 + grp + 8;
      float mm0 = -1e30f, mm1 = -1e30f;

      for (int jt8 = 0; jt8 < 8; jt8++) {
        const int j0 = nh * 128 + jt8 * 16;
        float x0[4] = {0,0,0,0}, y0[4] = {0,0,0,0};
        float x1[4] = {0,0,0,0}, y1[4] = {0,0,0,0};
#pragma unroll
        for (int kc = 0; kc < 4; kc++) {
          // B tiles order: (j0,c0),(j0,c1),(j0+8,c0),(j0+8,c1)
          int row = j0 + ((lg >> 1) << 3) + li;
          int ch  = kc*2 + (lg & 1);
          uint32_t off = (uint32_t)row*128 + (uint32_t)(((ch ^ li) & 7) << 4);
          uint32_t bh_[4], bl_[4];
          ldmx4(bh_, sb + AB_OPHI + off);
          ldmx4(bl_, sb + AB_OPLO + off);
          mma_bf16(x0, aq_hi[kc], bh_ + 0, x0);
          mma_bf16(y0, aq_lo[kc], bh_ + 0, y0);
          mma_bf16(y0, aq_hi[kc], bl_ + 0, y0);
          mma_bf16(x1, aq_hi[kc], bh_ + 2, x1);
          mma_bf16(y1, aq_lo[kc], bh_ + 2, y1);
          mma_bf16(y1, aq_hi[kc], bl_ + 2, y1);
        }
        float d00 = DS*(x0[0]+y0[0]), d01 = DS*(x0[1]+y0[1]);
        float d02 = DS*(x0[2]+y0[2]), d03 = DS*(x0[3]+y0[3]);
        float d10 = DS*(x1[0]+y1[0]), d11 = DS*(x1[1]+y1[1]);
        float d12 = DS*(x1[2]+y1[2]), d13 = DS*(x1[3]+y1[3]);
        mm0 = fmaxf(mm0, fmaxf(fmaxf(d00, d01), fmaxf(d10, d11)));
        mm1 = fmaxf(mm1, fmaxf(fmaxf(d02, d03), fmaxf(d12, d13)));
        float e00 = __expf(d00 - dnt0), e01 = __expf(d01 - dnt0);
        float e02 = __expf(d02 - dnt1), e03 = __expf(d03 - dnt1);
        float e10 = __expf(d10 - dnt0), e11 = __expf(d11 - dnt0);
        float e12 = __expf(d12 - dnt1), e13 = __expf(d13 - dnt1);

        const int ja = j0 + qd*2;
#pragma unroll
        for (int u = 0; u < 2; u++) {
          int j_0 = ja + u*8, j_1 = ja + u*8 + 1;
          float va0 = u ? e10 : e00, vb0 = u ? e11 : e01;
          float va1 = u ? e12 : e02, vb1 = u ? e13 : e03;
          uint32_t a00 = (uint32_t)j_0*128 + ((((ta >>3) ^ (j_0&7))<<4)) + (ta &7)*2;
          uint32_t a01 = (uint32_t)j_1*128 + ((((ta >>3) ^ (j_1&7))<<4)) + (ta &7)*2;
          uint32_t a10 = (uint32_t)j_0*128 + ((((tbq>>3) ^ (j_0&7))<<4)) + (tbq&7)*2;
          uint32_t a11 = (uint32_t)j_1*128 + ((((tbq>>3) ^ (j_1&7))<<4)) + (tbq&7)*2;
          sth(smc + AB_OSHI + a00, va0);  sth_lo(smc + AB_OSLO + a00, va0);
          sth(smc + AB_OSHI + a01, vb0);  sth_lo(smc + AB_OSLO + a01, vb0);
          sth(smc + AB_OSHI + a10, va1);  sth_lo(smc + AB_OSLO + a10, va1);
          sth(smc + AB_OSHI + a11, vb1);  sth_lo(smc + AB_OSLO + a11, vb1);
        }
      }
      mm0 = fmaxf(mm0, __shfl_xor_sync(0xffffffff, mm0, 1));
      mm0 = fmaxf(mm0, __shfl_xor_sync(0xffffffff, mm0, 2));
      mm1 = fmaxf(mm1, __shfl_xor_sync(0xffffffff, mm1, 1));
      mm1 = fmaxf(mm1, __shfl_xor_sync(0xffffffff, mm1, 2));
      if (qd == 0) {
        mx_s[(r0 + grp) * 2 + nh]     = mm0;
        mx_s[(r0 + grp + 8) * 2 + nh] = mm1;
      }
    }
    __syncthreads();

    // --- phase 3: w = exp(-rowmax) ---
    if (tid < 64) w_s[tid] = __expf(-fmaxf(mx_s[tid*2], mx_s[tid*2+1]));
    __syncthreads();

    // --- phase 4: v' = w*v transposed to vT[e][t]; w column at e=64 ---
    {
      const float4* vg = (const float4*)(vin + ((size_t)(bh*T_ + t0 + rq)) * DH_);
      float w = w_s[rq];
#pragma unroll
      for (int c = 0; c < 4; c++) {
        float4 v = vg[qtr*4 + c];
        v.x *= w; v.y *= w; v.z *= w; v.w *= w;
        int e0 = qtr*16 + c*4;
        float vv[4] = {v.x, v.y, v.z, v.w};
#pragma unroll
        for (int l = 0; l < 4; l++) {
          int e = e0 + l;
          uint32_t off = (uint32_t)e*128 + ((((rq>>3) ^ (e&7))<<4)) + (rq&7)*2;
          sth(smc + AB_OVHI + off, vv[l]);
          sth_lo(smc + AB_OVLO + off, vv[l]);
        }
      }
      if (tid < 64) {
        float w2 = w_s[tid];
        uint32_t off = (uint32_t)64*128 + (((tid>>3))<<4) + (tid&7)*2;
        sth(smc + AB_OVHI + off, w2);
        sth_lo(smc + AB_OVLO + off, w2);
      }
    }
    __syncthreads();

    // --- phase 5: MMA2: oacc += sT @ v' ---
#pragma unroll
    for (int mt2 = 0; mt2 < 2; mt2++) {
      const int jm = warp * 32 + mt2 * 16;
#pragma unroll
      for (int kc = 0; kc < 4; kc++) {
        uint32_t ash[4], asl[4];
        {
          int row = jm + ((lg & 1) << 3) + li;
          int ch  = kc*2 + (lg >> 1);
          uint32_t off = (uint32_t)row*128 + (uint32_t)(((ch ^ li) & 7) << 4);
          ldmx4(ash, sb + AB_OSHI + off);
          ldmx4(asl, sb + AB_OSLO + off);
        }
#pragma unroll
        for (int ntp = 0; ntp < 4; ntp++) {
          uint32_t bvh[4], bvl[4];
          int row = (ntp*2 + (lg >> 1))*8 + li;
          int ch  = kc*2 + (lg & 1);
          uint32_t off = (uint32_t)row*128 + (uint32_t)(((ch ^ li) & 7) << 4);
          ldmx4(bvh, sb + AB_OVHI + off);
          ldmx4(bvl, sb + AB_OVLO + off);
          int nt0 = ntp*2, nt1 = ntp*2 + 1;
          mma_bf16(oacc[mt2][nt0], ash, bvh + 0, oacc[mt2][nt0]);
          mma_bf16(oacc[mt2][nt0], asl, bvh + 0, oacc[mt2][nt0]);
          mma_bf16(oacc[mt2][nt0], ash, bvl + 0, oacc[mt2][nt0]);
          mma_bf16(oacc[mt2][nt1], ash, bvh + 2, oacc[mt2][nt1]);
          mma_bf16(oacc[mt2][nt1], asl, bvh + 2, oacc[mt2][nt1]);
          mma_bf16(oacc[mt2][nt1], ash, bvl + 2, oacc[mt2][nt1]);
        }
        // nt = 8 (scalar B loads, rows 64..71)
        {
          uint32_t c0 = (uint32_t)(((kc*2)     ^ grp) << 4);
          uint32_t c1 = (uint32_t)(((kc*2 + 1) ^ grp) << 4);
          uint32_t rb = (uint32_t)(64 + grp) * 128u + (uint32_t)(qd * 4);
          uint32_t bvh[2] = { *(uint32_t*)(smc + AB_OVHI + rb + c0),
                              *(uint32_t*)(smc + AB_OVHI + rb + c1) };
          uint32_t bvl[2] = { *(uint32_t*)(smc + AB_OVLO + rb + c0),
                              *(uint32_t*)(smc + AB_OVLO + rb + c1) };
          mma_bf16(oacc[mt2][8], ash, bvh, oacc[mt2][8]);
          mma_bf16(oacc[mt2][8], asl, bvh, oacc[mt2][8]);
          mma_bf16(oacc[mt2][8], ash, bvl, oacc[mt2][8]);
        }
      }
    }
  }

  // --- final: store partial to g_ctx_part[xb][bh][e][j] ---
  float* ctxp = g_ctx_part + ((size_t)blockIdx.x * BH_ + bh) * 72 * NF_;
#pragma unroll
  for (int mt2 = 0; mt2 < 2; mt2++)
#pragma unroll
    for (int nt = 0; nt < 9; nt++)
#pragma unroll
      for (int c = 0; c < 4; c++) {
        int j = warp*32 + mt2*16 + grp + ((c >= 2) ? 8 : 0);
        int e = nt*8 + qd*2 + (c & 1);
        if (e < 65) ctxp[e * NF_ + j] = oacc[mt2][nt][c];
      }
}

// ---------------------------------------------------------------------------
// Kernel C with ldmatrix fragment loads
#define OQHI  0
#define OQLO  16384
#define OPHI  32768
#define OPLO  65536
#define OCHI  98304
#define OCLO  131072
#define OKS   163840
#define ODN   164864
#define SMEMC 165504

__global__ __launch_bounds__(256, 1)
void kernelC(const float* __restrict__ qin,
             const float* __restrict__ proj,
             float* __restrict__ outg) {
  extern __shared__ char smc[];
  const uint32_t sb = smem_u32(smc);
  float* ks_s = (float*)(smc + OKS);
  float* dn_s = (float*)(smc + ODN);

  const int tid  = threadIdx.x;
  const int warp = tid >> 5;
  const int lane = tid & 31;
  const int grp  = lane >> 2;
  const int qd   = lane & 3;
  const int lg   = lane >> 3;
  const int li   = lane & 7;
  const int bh   = blockIdx.y;
  const int t0   = blockIdx.x * 128;

  {
    const float4* pg = (const float4*)proj;
#pragma unroll
    for (int it = 0; it < 16; it++) {
      int i = tid + it * 256;
      int row = i >> 4, kp = (i & 15) * 4;
      uint32_t off = (uint32_t)row*128 + (uint32_t)(((kp>>3) ^ (row&7)) << 4)
                   + (uint32_t)((kp&7)*2);
      uint2 hi, lo; cvt_hilo(pg[i], hi, lo);
      *(uint2*)(smc + OPHI + off) = hi;
      *(uint2*)(smc + OPLO + off) = lo;
    }
  }
  {
    const float4* cg = (const float4*)(g_ctx + bh * 72 * NF_);
#pragma unroll
    for (int it = 0; it < 16; it++) {
      int i = tid + it * 256;
      int e = i >> 6, j4 = (i & 63) * 4;
      int ch = j4 >> 3;
      int swc = (ch & 24) | ((ch ^ e) & 7);
      uint32_t off = (uint32_t)e*512 + (uint32_t)(swc << 4) + (uint32_t)((j4&7)*2);
      uint2 hi, lo; cvt_hilo(cg[i], hi, lo);
      *(uint2*)(smc + OCHI + off) = hi;
      *(uint2*)(smc + OCLO + off) = lo;
    }
  }
  {
    const int rq = tid >> 1, half = tid & 1;
    const float4* qg = (const float4*)(qin + ((size_t)(bh * T_ + t0 + rq)) * DH_);
    float dsum = 0.f;
#pragma unroll
    for (int c = 0; c < 8; c++) {
      float4 v = qg[half*8 + c];
      dsum += v.x*v.x + v.y*v.y + v.z*v.z + v.w*v.w;
      int kp = half*32 + c*4;
      uint32_t off = (uint32_t)rq*128 + (uint32_t)(((kp>>3) ^ (rq&7)) << 4)
                   + (uint32_t)((kp&7)*2);
      uint2 hi, lo; cvt_hilo(v, hi, lo);
      *(uint2*)(smc + OQHI + off) = hi;
      *(uint2*)(smc + OQLO + off) = lo;
    }
    dsum += __shfl_xor_sync(0xffffffff, dsum, 1);
    if (half == 0) dn_s[rq] = dsum;
  }
  ks_s[tid] = g_ctx[bh * 72 * NF_ + 64 * NF_ + tid];
  __syncthreads();

  const int r0 = warp * 16;
  uint32_t aq_hi[4][4], aq_lo[4][4];
#pragma unroll
  for (int kc = 0; kc < 4; kc++) {
    int row = r0 + ((lg & 1) << 3) + li;
    int ch  = kc*2 + (lg >> 1);
    uint32_t off = (uint32_t)row*128 + (uint32_t)(((ch ^ li) & 7) << 4);
    ldmx4(aq_hi[kc], sb + OQHI + off);
    ldmx4(aq_lo[kc], sb + OQLO + off);
  }

  float oacc[8][4];
#pragma unroll
  for (int et = 0; et < 8; et++)
#pragma unroll
    for (int i = 0; i < 4; i++) oacc[et][i] = 0.f;

  float den0 = 0.f, den1 = 0.f;
  const float dnt0 = DNC * dn_s[r0 + grp];
  const float dnt1 = DNC * dn_s[r0 + grp + 8];

  for (int jt = 0; jt < 16; jt++) {
    const int j0 = jt * 16;
    float x0[4] = {0,0,0,0}, y0[4] = {0,0,0,0};
    float x1[4] = {0,0,0,0}, y1[4] = {0,0,0,0};
#pragma unroll
    for (int kc = 0; kc < 4; kc++) {
      int row = j0 + ((lg >> 1) << 3) + li;
      int ch  = kc*2 + (lg & 1);
      uint32_t off = (uint32_t)row*128 + (uint32_t)(((ch ^ li) & 7) << 4);
      uint32_t bh_[4], bl_[4];
      ldmx4(bh_, sb + OPHI + off);
      ldmx4(bl_, sb + OPLO + off);
      mma_bf16(x0, aq_hi[kc], bh_ + 0, x0);
      mma_bf16(y0, aq_lo[kc], bh_ + 0, y0);
      mma_bf16(y0, aq_hi[kc], bl_ + 0, y0);
      mma_bf16(x1, aq_hi[kc], bh_ + 2, x1);
      mma_bf16(y1, aq_lo[kc], bh_ + 2, y1);
      mma_bf16(y1, aq_hi[kc], bl_ + 2, y1);
    }

    float e00 = __expf(fmaf(DS, x0[0] + y0[0], -dnt0));
    float e01 = __expf(fmaf(DS, x0[1] + y0[1], -dnt0));
    float e02 = __expf(fmaf(DS, x0[2] + y0[2], -dnt1));
    float e03 = __expf(fmaf(DS, x0[3] + y0[3], -dnt1));
    float e10 = __expf(fmaf(DS, x1[0] + y1[0], -dnt0));
    float e11 = __expf(fmaf(DS, x1[1] + y1[1], -dnt0));
    float e12 = __expf(fmaf(DS, x1[2] + y1[2], -dnt1));
    float e13 = __expf(fmaf(DS, x1[3] + y1[3], -dnt1));

    float2 kv0 = *(float2*)(ks_s + j0 + qd*2);
    float2 kv1 = *(float2*)(ks_s + j0 + 8 + qd*2);
    den0 = fmaf(e00, kv0.x, fmaf(e01, kv0.y, fmaf(e10, kv1.x, fmaf(e11, kv1.y, den0))));
    den1 = fmaf(e02, kv0.x, fmaf(e03, kv0.y, fmaf(e12, kv1.x, fmaf(e13, kv1.y, den1))));

    __nv_bfloat16 h00 = __float2bfloat16(e00), h01 = __float2bfloat16(e01);
    __nv_bfloat16 h02 = __float2bfloat16(e02), h03 = __float2bfloat16(e03);
    __nv_bfloat16 h10 = __float2bfloat16(e10), h11 = __float2bfloat16(e11);
    __nv_bfloat16 h12 = __float2bfloat16(e12), h13 = __float2bfloat16(e13);
    uint32_t qa_hi[4] = { packb(h00, h01), packb(h02, h03),
                          packb(h10, h11), packb(h12, h13) };
    uint32_t qa_lo[4] = {
      packb(__float2bfloat16(e00 - __bfloat162float(h00)),
            __float2bfloat16(e01 - __bfloat162float(h01))),
      packb(__float2bfloat16(e02 - __bfloat162float(h02)),
            __float2bfloat16(e03 - __bfloat162float(h03))),
      packb(__float2bfloat16(e10 - __bfloat162float(h10)),
            __float2bfloat16(e11 - __bfloat162float(h11))),
      packb(__float2bfloat16(e12 - __bfloat162float(h12)),
            __float2bfloat16(e13 - __bfloat162float(h13))) };

    const int ch0 = jt * 2;
#pragma unroll
    for (int etp = 0; etp < 4; etp++) {
      uint32_t bh_[4], bl_[4];
      int e = (etp*2 + (lg >> 1))*8 + li;
      int ch = ch0 + (lg & 1);
      uint32_t off = (uint32_t)e*512
                   + (uint32_t)((((ch & 24) | ((ch ^ li) & 7))) << 4);
      ldmx4(bh_, sb + OCHI + off);
      ldmx4(bl_, sb + OCLO + off);
      int et0 = etp*2, et1 = etp*2 + 1;
      mma_bf16(oacc[et0], qa_hi, bh_ + 0, oacc[et0]);
      mma_bf16(oacc[et0], qa_lo, bh_ + 0, oacc[et0]);
      mma_bf16(oacc[et0], qa_hi, bl_ + 0, oacc[et0]);
      mma_bf16(oacc[et1], qa_hi, bh_ + 2, oacc[et1]);
      mma_bf16(oacc[et1], qa_lo, bh_ + 2, oacc[et1]);
      mma_bf16(oacc[et1], qa_hi, bl_ + 2, oacc[et1]);
    }
  }

  den0 += __shfl_xor_sync(0xffffffff, den0, 1);
  den0 += __shfl_xor_sync(0xffffffff, den0, 2);
  den1 += __shfl_xor_sync(0xffffffff, den1, 1);
  den1 += __shfl_xor_sync(0xffffffff, den1, 2);
  float inv0 = 1.f / den0, inv1 = 1.f / den1;

  float* og0 = outg + ((size_t)(bh * T_ + t0 + r0 + grp)) * DH_;
  float* og1 = og0 + 8 * DH_;
#pragma unroll
  for (int et = 0; et < 8; et++) {
    int col = et * 8 + qd * 2;
    *(float2*)(og0 + col) = make_float2(oacc[et][0] * inv0, oacc[et][1] * inv0);
    *(float2*)(og1 + col) = make_float2(oacc[et][2] * inv1, oacc[et][3] * inv1);
  }
}

// ---------------------------------------------------------------------------
extern "C" void kernel_launch(void* const* d_in, const int* in_sizes, int n_in,
                              void* d_out, int out_size) {
  const float* q    = (const float*)d_in[0];
  const float* k    = (const float*)d_in[1];
  const float* v    = (const float*)d_in[2];
  const float* proj = (const float*)d_in[3];
  float* out = (float*)d_out;

  cudaFuncSetAttribute(kernelAB, cudaFuncAttributeMaxDynamicSharedMemorySize, SMEMAB);
  cudaFuncSetAttribute(kernelC,  cudaFuncAttributeMaxDynamicSharedMemorySize, SMEMC);

  kernelAB<<<dim3(8, BH_), 256, SMEMAB>>>(k, v, proj);
  reduce_kernel<<<(BH_*65*NF_ + 255)/256, 256>>>();
  kernelC<<<dim3(T_/128, BH_), 256, SMEMC>>>(q, proj, out);
}

// round 14
// speedup vs baseline: 3.0162x; 1.0550x over previous
#include <cuda_runtime.h>
#include <cuda_bf16.h>
#include <math.h>
#include <cstdint>

#define T_  4096
#define NF_ 256
#define DH_ 64
#define BH_ 64
#define DS  0.35355339059327373f
#define DNC 0.0625f

// per-xb partial ctx: [xb=8][bh][e'=72][j=256] (only e<65 written/read)
__device__ float g_ctx_part[8 * BH_ * 72 * NF_];
// reduced ctx+ksum: [bh][e'=72][j=256], row 64 = ksum
__device__ float g_ctx[BH_ * 72 * NF_];

__device__ __forceinline__ uint32_t smem_u32(const void* p) {
  uint32_t a;
  asm("{ .reg .u64 tmp; cvta.to.shared.u64 tmp, %1; cvt.u32.u64 %0, tmp; }"
      : "=r"(a) : "l"(p));
  return a;
}

__device__ __forceinline__ void ldmx4(uint32_t* r, uint32_t addr) {
  asm volatile("ldmatrix.sync.aligned.m8n8.x4.shared.b16 {%0,%1,%2,%3}, [%4];"
      : "=r"(r[0]), "=r"(r[1]), "=r"(r[2]), "=r"(r[3]) : "r"(addr));
}

__device__ __forceinline__ uint32_t packb(__nv_bfloat16 a, __nv_bfloat16 b) {
  __nv_bfloat162 t(a, b);
  return *reinterpret_cast<uint32_t*>(&t);
}

__device__ __forceinline__ void cvt_hilo(float4 v, uint2& hi, uint2& lo) {
  __nv_bfloat16 h0 = __float2bfloat16(v.x), h1 = __float2bfloat16(v.y);
  __nv_bfloat16 h2 = __float2bfloat16(v.z), h3 = __float2bfloat16(v.w);
  hi = make_uint2(packb(h0, h1), packb(h2, h3));
  lo = make_uint2(packb(__float2bfloat16(v.x - __bfloat162float(h0)),
                        __float2bfloat16(v.y - __bfloat162float(h1))),
                  packb(__float2bfloat16(v.z - __bfloat162float(h2)),
                        __float2bfloat16(v.w - __bfloat162float(h3))));
}

// m16n8k16 row.col bf16 -> f32
__device__ __forceinline__ void mma_bf16(float* d, const uint32_t* a,
                                         const uint32_t* b, const float* c) {
  asm volatile(
      "mma.sync.aligned.m16n8k16.row.col.f32.bf16.bf16.f32 "
      "{%0,%1,%2,%3}, {%4,%5,%6,%7}, {%8,%9}, {%10,%11,%12,%13};"
      : "=f"(d[0]), "=f"(d[1]), "=f"(d[2]), "=f"(d[3])
      : "r"(a[0]), "r"(a[1]), "r"(a[2]), "r"(a[3]),
        "r"(b[0]), "r"(b[1]),
        "f"(c[0]), "f"(c[1]), "f"(c[2]), "f"(c[3]));
}

__device__ __forceinline__ void sth(void* p, float v) {
  __nv_bfloat16 h = __float2bfloat16(v);
  *(__nv_bfloat16*)p = h;
}
__device__ __forceinline__ void sth_lo(void* p, float v) {
  __nv_bfloat16 h = __float2bfloat16(v);
  *(__nv_bfloat16*)p = __float2bfloat16(v - __bfloat162float(h));
}

// ---------------------------------------------------------------------------
// Reduce 8 partials -> g_ctx (covers e 0..64; rows 65-71 never read)
__global__ void reduce_kernel() {
  int idx = blockIdx.x * blockDim.x + threadIdx.x;
  const int n = BH_ * 65 * NF_;
  if (idx >= n) return;
  int bh = idx / (65 * NF_);
  int rem = idx % (65 * NF_);
  const size_t stride = (size_t)BH_ * 72 * NF_;
  const float* p = g_ctx_part + (size_t)bh * 72 * NF_ + rem;
  float s = 0.f;
#pragma unroll
  for (int xb = 0; xb < 8; xb++) s += p[xb * stride];
  g_ctx[bh * 72 * NF_ + rem] = s;
}

// ---------------------------------------------------------------------------
// Fused kernel AB (transposed MMA1): per block 512 tokens of one bh.
//   MMA1: dpT[j][t] = proj @ k^T  (A=proj m=j, B=k n=t, k=d)
//   exp in registers; accumulator IS the A-fragment of MMA2 (identity).
//   rowmax over j via shfl + per-warp smem; w=exp(-max) folded into v'.
//   MMA2: ctx[j][e'] += sT @ v' (e'=64 column = w -> ksum).
#define AB_OPHI 0
#define AB_OPLO 32768
#define AB_OKHI 65536
#define AB_OKLO 73728
#define AB_OVHI 81920
#define AB_OVLO 91136
#define AB_OW   100352
#define AB_ODN  100608
#define AB_OMX  100864
#define SMEMAB  102912

__global__ __launch_bounds__(256, 1)
void kernelAB(const float* __restrict__ kin,
              const float* __restrict__ vin,
              const float* __restrict__ proj) {
  extern __shared__ char smc[];
  const uint32_t sb = smem_u32(smc);
  float* w_s   = (float*)(smc + AB_OW);
  float* dn_s  = (float*)(smc + AB_ODN);
  float* mxw_s = (float*)(smc + AB_OMX);   // [8 warps][64 t]

  const int tid  = threadIdx.x;
  const int warp = tid >> 5;
  const int lane = tid & 31;
  const int grp  = lane >> 2;
  const int qd   = lane & 3;
  const int lg   = lane >> 3;
  const int li   = lane & 7;
  const int bh   = blockIdx.y;
  const int tb   = blockIdx.x * 512;

  // --- proj [256 j][64 d] -> bf16 hi/lo, 128B swizzled rows ---
  {
    const float4* pg = (const float4*)proj;
#pragma unroll
    for (int it = 0; it < 16; it++) {
      int i = tid + it * 256;
      int row = i >> 4, kp = (i & 15) * 4;
      uint32_t off = (uint32_t)row*128 + (uint32_t)(((kp>>3) ^ (row&7)) << 4)
                   + (uint32_t)((kp&7)*2);
      uint2 hi, lo; cvt_hilo(pg[i], hi, lo);
      *(uint2*)(smc + AB_OPHI + off) = hi;
      *(uint2*)(smc + AB_OPLO + off) = lo;
    }
  }
  // --- zero v' rows 65..71 ---
  for (int i = tid; i < 448; i += 256) {
    *(uint16_t*)(smc + AB_OVHI + 65*128 + i*2) = 0;
    *(uint16_t*)(smc + AB_OVLO + 65*128 + i*2) = 0;
  }

  float oacc[2][9][4];
#pragma unroll
  for (int a = 0; a < 2; a++)
#pragma unroll
    for (int b = 0; b < 9; b++)
#pragma unroll
      for (int c = 0; c < 4; c++) oacc[a][b][c] = 0.f;

  const int rq  = tid >> 2;
  const int qtr = tid & 3;

  for (int it = 0; it < 8; it++) {
    const int t0 = tb + it * 64;
    __syncthreads();

    // --- phase 1: k subtile [64 t][64 d] -> smem hi/lo + dn ---
    {
      const float4* kg = (const float4*)(kin + ((size_t)(bh*T_ + t0 + rq)) * DH_);
      float dsum = 0.f;
#pragma unroll
      for (int c = 0; c < 4; c++) {
        float4 v = kg[qtr*4 + c];
        dsum += v.x*v.x + v.y*v.y + v.z*v.z + v.w*v.w;
        int g4 = qtr*4 + c;
        uint32_t off = (uint32_t)rq*128
                     + (uint32_t)((((g4>>1) ^ (rq&7)) << 4)) + (uint32_t)((g4&1)*8);
        uint2 hi, lo; cvt_hilo(v, hi, lo);
        *(uint2*)(smc + AB_OKHI + off) = hi;
        *(uint2*)(smc + AB_OKLO + off) = lo;
      }
      dsum += __shfl_xor_sync(0xffffffff, dsum, 1);
      dsum += __shfl_xor_sync(0xffffffff, dsum, 2);
      if (qtr == 0) dn_s[rq] = dsum;
    }
    __syncthreads();

    // --- phase 2: MMA1 (dpT = proj @ k^T) + exp + qa pack + rowmax ---
    uint32_t qa_hi[2][4][4], qa_lo[2][4][4];   // [mt][kchunk][frag]
#pragma unroll
    for (int mt = 0; mt < 2; mt++) {
      const int j0 = warp * 32 + mt * 16;
      uint32_t ap_hi[4][4], ap_lo[4][4];
#pragma unroll
      for (int kc = 0; kc < 4; kc++) {
        int row = j0 + ((lg & 1) << 3) + li;
        int ch  = kc*2 + (lg >> 1);
        uint32_t off = (uint32_t)row*128 + (uint32_t)(((ch ^ li) & 7) << 4);
        ldmx4(ap_hi[kc], sb + AB_OPHI + off);
        ldmx4(ap_lo[kc], sb + AB_OPLO + off);
      }
#pragma unroll
      for (int ntp = 0; ntp < 4; ntp++) {
        float x0[4] = {0,0,0,0}, y0[4] = {0,0,0,0};
        float x1[4] = {0,0,0,0}, y1[4] = {0,0,0,0};
#pragma unroll
        for (int kc = 0; kc < 4; kc++) {
          int row = ntp*16 + ((lg >> 1) << 3) + li;
          int ch  = kc*2 + (lg & 1);
          uint32_t off = (uint32_t)row*128 + (uint32_t)(((ch ^ li) & 7) << 4);
          uint32_t bh_[4], bl_[4];
          ldmx4(bh_, sb + AB_OKHI + off);
          ldmx4(bl_, sb + AB_OKLO + off);
          mma_bf16(x0, ap_hi[kc], bh_ + 0, x0);
          mma_bf16(y0, ap_lo[kc], bh_ + 0, y0);
          mma_bf16(y0, ap_hi[kc], bl_ + 0, y0);
          mma_bf16(x1, ap_hi[kc], bh_ + 2, x1);
          mma_bf16(y1, ap_lo[kc], bh_ + 2, y1);
          mma_bf16(y1, ap_hi[kc], bl_ + 2, y1);
        }
        // dpT elements: rows j0+grp / j0+grp+8; cols t = 16ntp+2qd(+1), +8
        float d00 = DS*(x0[0]+y0[0]), d01 = DS*(x0[1]+y0[1]);
        float d02 = DS*(x0[2]+y0[2]), d03 = DS*(x0[3]+y0[3]);
        float d10 = DS*(x1[0]+y1[0]), d11 = DS*(x1[1]+y1[1]);
        float d12 = DS*(x1[2]+y1[2]), d13 = DS*(x1[3]+y1[3]);

        float2 dnA = *(float2*)(dn_s + 16*ntp + 2*qd);
        float2 dnB = *(float2*)(dn_s + 16*ntp + 8 + 2*qd);
        float e00 = __expf(d00 - DNC*dnA.x), e01 = __expf(d01 - DNC*dnA.y);
        float e02 = __expf(d02 - DNC*dnA.x), e03 = __expf(d03 - DNC*dnA.y);
        float e10 = __expf(d10 - DNC*dnB.x), e11 = __expf(d11 - DNC*dnB.y);
        float e12 = __expf(d12 - DNC*dnB.x), e13 = __expf(d13 - DNC*dnB.y);

        // per-t max over this warp's 32 j rows
        float mA0 = fmaxf(d00, d02), mA1 = fmaxf(d01, d03);
        float mB0 = fmaxf(d10, d12), mB1 = fmaxf(d11, d13);
#pragma unroll
        for (int s = 4; s < 32; s <<= 1) {
          mA0 = fmaxf(mA0, __shfl_xor_sync(0xffffffff, mA0, s));
          mA1 = fmaxf(mA1, __shfl_xor_sync(0xffffffff, mA1, s));
          mB0 = fmaxf(mB0, __shfl_xor_sync(0xffffffff, mB0, s));
          mB1 = fmaxf(mB1, __shfl_xor_sync(0xffffffff, mB1, s));
        }
        if (grp == 0) {
          float* mw = mxw_s + warp*64 + 16*ntp + 2*qd;
          if (mt == 0) {
            mw[0] = mA0; mw[1] = mA1; mw[8] = mB0; mw[9] = mB1;
          } else {
            mw[0] = fmaxf(mw[0], mA0); mw[1] = fmaxf(mw[1], mA1);
            mw[8] = fmaxf(mw[8], mB0); mw[9] = fmaxf(mw[9], mB1);
          }
        }

        // accumulator -> A-fragment identity (k-chunk = ntp)
        __nv_bfloat16 h00 = __float2bfloat16(e00), h01 = __float2bfloat16(e01);
        __nv_bfloat16 h02 = __float2bfloat16(e02), h03 = __float2bfloat16(e03);
        __nv_bfloat16 h10 = __float2bfloat16(e10), h11 = __float2bfloat16(e11);
        __nv_bfloat16 h12 = __float2bfloat16(e12), h13 = __float2bfloat16(e13);
        qa_hi[mt][ntp][0] = packb(h00, h01);
        qa_hi[mt][ntp][1] = packb(h02, h03);
        qa_hi[mt][ntp][2] = packb(h10, h11);
        qa_hi[mt][ntp][3] = packb(h12, h13);
        qa_lo[mt][ntp][0] = packb(__float2bfloat16(e00 - __bfloat162float(h00)),
                                  __float2bfloat16(e01 - __bfloat162float(h01)));
        qa_lo[mt][ntp][1] = packb(__float2bfloat16(e02 - __bfloat162float(h02)),
                                  __float2bfloat16(e03 - __bfloat162float(h03)));
        qa_lo[mt][ntp][2] = packb(__float2bfloat16(e10 - __bfloat162float(h10)),
                                  __float2bfloat16(e11 - __bfloat162float(h11)));
        qa_lo[mt][ntp][3] = packb(__float2bfloat16(e12 - __bfloat162float(h12)),
                                  __float2bfloat16(e13 - __bfloat162float(h13)));
      }
    }
    __syncthreads();

    // --- phase 3: w = exp(-max over all 256 j) ---
    if (tid < 64) {
      float m = mxw_s[tid];
#pragma unroll
      for (int w = 1; w < 8; w++) m = fmaxf(m, mxw_s[w*64 + tid]);
      w_s[tid] = __expf(-m);
    }
    __syncthreads();

    // --- phase 4: v' = w*v transposed to vT[e][t]; w column at e=64 ---
    {
      const float4* vg = (const float4*)(vin + ((size_t)(bh*T_ + t0 + rq)) * DH_);
      float w = w_s[rq];
#pragma unroll
      for (int c = 0; c < 4; c++) {
        float4 v = vg[qtr*4 + c];
        v.x *= w; v.y *= w; v.z *= w; v.w *= w;
        int e0 = qtr*16 + c*4;
        float vv[4] = {v.x, v.y, v.z, v.w};
#pragma unroll
        for (int l = 0; l < 4; l++) {
          int e = e0 + l;
          uint32_t off = (uint32_t)e*128 + ((((rq>>3) ^ (e&7))<<4)) + (rq&7)*2;
          sth(smc + AB_OVHI + off, vv[l]);
          sth_lo(smc + AB_OVLO + off, vv[l]);
        }
      }
      if (tid < 64) {
        float w2 = w_s[tid];
        uint32_t off = (uint32_t)64*128 + (((tid>>3))<<4) + (tid&7)*2;
        sth(smc + AB_OVHI + off, w2);
        sth_lo(smc + AB_OVLO + off, w2);
      }
    }
    __syncthreads();

    // --- phase 5: MMA2: oacc += sT @ v' (A = qa registers) ---
#pragma unroll
    for (int kc = 0; kc < 4; kc++) {
#pragma unroll
      for (int ntp = 0; ntp < 4; ntp++) {
        uint32_t bvh[4], bvl[4];
        int row = ntp*16 + ((lg >> 1) << 3) + li;
        int ch  = kc*2 + (lg & 1);
        uint32_t off = (uint32_t)row*128 + (uint32_t)(((ch ^ li) & 7) << 4);
        ldmx4(bvh, sb + AB_OVHI + off);
        ldmx4(bvl, sb + AB_OVLO + off);
#pragma unroll
        for (int mt = 0; mt < 2; mt++) {
          int nt0 = ntp*2, nt1 = ntp*2 + 1;
          mma_bf16(oacc[mt][nt0], qa_hi[mt][kc], bvh + 0, oacc[mt][nt0]);
          mma_bf16(oacc[mt][nt0], qa_lo[mt][kc], bvh + 0, oacc[mt][nt0]);
          mma_bf16(oacc[mt][nt0], qa_hi[mt][kc], bvl + 0, oacc[mt][nt0]);
          mma_bf16(oacc[mt][nt1], qa_hi[mt][kc], bvh + 2, oacc[mt][nt1]);
          mma_bf16(oacc[mt][nt1], qa_lo[mt][kc], bvh + 2, oacc[mt][nt1]);
          mma_bf16(oacc[mt][nt1], qa_hi[mt][kc], bvl + 2, oacc[mt][nt1]);
        }
      }
      // nt = 8 (e rows 64..71, scalar B loads)
      {
        uint32_t c0 = (uint32_t)(((kc*2)     ^ grp) << 4);
        uint32_t c1 = (uint32_t)(((kc*2 + 1) ^ grp) << 4);
        uint32_t rb = (uint32_t)(64 + grp) * 128u + (uint32_t)(qd * 4);
        uint32_t bvh[2] = { *(uint32_t*)(smc + AB_OVHI + rb + c0),
                            *(uint32_t*)(smc + AB_OVHI + rb + c1) };
        uint32_t bvl[2] = { *(uint32_t*)(smc + AB_OVLO + rb + c0),
                            *(uint32_t*)(smc + AB_OVLO + rb + c1) };
#pragma unroll
        for (int mt = 0; mt < 2; mt++) {
          mma_bf16(oacc[mt][8], qa_hi[mt][kc], bvh, oacc[mt][8]);
          mma_bf16(oacc[mt][8], qa_lo[mt][kc], bvh, oacc[mt][8]);
          mma_bf16(oacc[mt][8], qa_hi[mt][kc], bvl, oacc[mt][8]);
        }
      }
    }
  }

  // --- final: store partial to g_ctx_part[xb][bh][e][j] ---
  float* ctxp = g_ctx_part + ((size_t)blockIdx.x * BH_ + bh) * 72 * NF_;
#pragma unroll
  for (int mt = 0; mt < 2; mt++)
#pragma unroll
    for (int nt = 0; nt < 9; nt++)
#pragma unroll
      for (int c = 0; c < 4; c++) {
        int j = warp*32 + mt*16 + grp + ((c >= 2) ? 8 : 0);
        int e = nt*8 + qd*2 + (c & 1);
        if (e < 65) ctxp[e * NF_ + j] = oacc[mt][nt][c];
      }
}

// ---------------------------------------------------------------------------
// Kernel C (unchanged from R13)
#define OQHI  0
#define OQLO  16384
#define OPHI  32768
#define OPLO  65536
#define OCHI  98304
#define OCLO  131072
#define OKS   163840
#define ODN   164864
#define SMEMC 165504

__global__ __launch_bounds__(256, 1)
void kernelC(const float* __restrict__ qin,
             const float* __restrict__ proj,
             float* __restrict__ outg) {
  extern __shared__ char smc[];
  const uint32_t sb = smem_u32(smc);
  float* ks_s = (float*)(smc + OKS);
  float* dn_s = (float*)(smc + ODN);

  const int tid  = threadIdx.x;
  const int warp = tid >> 5;
  const int lane = tid & 31;
  const int grp  = lane >> 2;
  const int qd   = lane & 3;
  const int lg   = lane >> 3;
  const int li   = lane & 7;
  const int bh   = blockIdx.y;
  const int t0   = blockIdx.x * 128;

  {
    const float4* pg = (const float4*)proj;
#pragma unroll
    for (int it = 0; it < 16; it++) {
      int i = tid + it * 256;
      int row = i >> 4, kp = (i & 15) * 4;
      uint32_t off = (uint32_t)row*128 + (uint32_t)(((kp>>3) ^ (row&7)) << 4)
                   + (uint32_t)((kp&7)*2);
      uint2 hi, lo; cvt_hilo(pg[i], hi, lo);
      *(uint2*)(smc + OPHI + off) = hi;
      *(uint2*)(smc + OPLO + off) = lo;
    }
  }
  {
    const float4* cg = (const float4*)(g_ctx + bh * 72 * NF_);
#pragma unroll
    for (int it = 0; it < 16; it++) {
      int i = tid + it * 256;
      int e = i >> 6, j4 = (i & 63) * 4;
      int ch = j4 >> 3;
      int swc = (ch & 24) | ((ch ^ e) & 7);
      uint32_t off = (uint32_t)e*512 + (uint32_t)(swc << 4) + (uint32_t)((j4&7)*2);
      uint2 hi, lo; cvt_hilo(cg[i], hi, lo);
      *(uint2*)(smc + OCHI + off) = hi;
      *(uint2*)(smc + OCLO + off) = lo;
    }
  }
  {
    const int rq = tid >> 1, half = tid & 1;
    const float4* qg = (const float4*)(qin + ((size_t)(bh * T_ + t0 + rq)) * DH_);
    float dsum = 0.f;
#pragma unroll
    for (int c = 0; c < 8; c++) {
      float4 v = qg[half*8 + c];
      dsum += v.x*v.x + v.y*v.y + v.z*v.z + v.w*v.w;
      int kp = half*32 + c*4;
      uint32_t off = (uint32_t)rq*128 + (uint32_t)(((kp>>3) ^ (rq&7)) << 4)
                   + (uint32_t)((kp&7)*2);
      uint2 hi, lo; cvt_hilo(v, hi, lo);
      *(uint2*)(smc + OQHI + off) = hi;
      *(uint2*)(smc + OQLO + off) = lo;
    }
    dsum += __shfl_xor_sync(0xffffffff, dsum, 1);
    if (half == 0) dn_s[rq] = dsum;
  }
  ks_s[tid] = g_ctx[bh * 72 * NF_ + 64 * NF_ + tid];
  __syncthreads();

  const int r0 = warp * 16;
  uint32_t aq_hi[4][4], aq_lo[4][4];
#pragma unroll
  for (int kc = 0; kc < 4; kc++) {
    int row = r0 + ((lg & 1) << 3) + li;
    int ch  = kc*2 + (lg >> 1);
    uint32_t off = (uint32_t)row*128 + (uint32_t)(((ch ^ li) & 7) << 4);
    ldmx4(aq_hi[kc], sb + OQHI + off);
    ldmx4(aq_lo[kc], sb + OQLO + off);
  }

  float oacc[8][4];
#pragma unroll
  for (int et = 0; et < 8; et++)
#pragma unroll
    for (int i = 0; i < 4; i++) oacc[et][i] = 0.f;

  float den0 = 0.f, den1 = 0.f;
  const float dnt0 = DNC * dn_s[r0 + grp];
  const float dnt1 = DNC * dn_s[r0 + grp + 8];

  for (int jt = 0; jt < 16; jt++) {
    const int j0 = jt * 16;
    float x0[4] = {0,0,0,0}, y0[4] = {0,0,0,0};
    float x1[4] = {0,0,0,0}, y1[4] = {0,0,0,0};
#pragma unroll
    for (int kc = 0; kc < 4; kc++) {
      int row = j0 + ((lg >> 1) << 3) + li;
      int ch  = kc*2 + (lg & 1);
      uint32_t off = (uint32_t)row*128 + (uint32_t)(((ch ^ li) & 7) << 4);
      uint32_t bh_[4], bl_[4];
      ldmx4(bh_, sb + OPHI + off);
      ldmx4(bl_, sb + OPLO + off);
      mma_bf16(x0, aq_hi[kc], bh_ + 0, x0);
      mma_bf16(y0, aq_lo[kc], bh_ + 0, y0);
      mma_bf16(y0, aq_hi[kc], bl_ + 0, y0);
      mma_bf16(x1, aq_hi[kc], bh_ + 2, x1);
      mma_bf16(y1, aq_lo[kc], bh_ + 2, y1);
      mma_bf16(y1, aq_hi[kc], bl_ + 2, y1);
    }

    float e00 = __expf(fmaf(DS, x0[0] + y0[0], -dnt0));
    float e01 = __expf(fmaf(DS, x0[1] + y0[1], -dnt0));
    float e02 = __expf(fmaf(DS, x0[2] + y0[2], -dnt1));
    float e03 = __expf(fmaf(DS, x0[3] + y0[3], -dnt1));
    float e10 = __expf(fmaf(DS, x1[0] + y1[0], -dnt0));
    float e11 = __expf(fmaf(DS, x1[1] + y1[1], -dnt0));
    float e12 = __expf(fmaf(DS, x1[2] + y1[2], -dnt1));
    float e13 = __expf(fmaf(DS, x1[3] + y1[3], -dnt1));

    float2 kv0 = *(float2*)(ks_s + j0 + qd*2);
    float2 kv1 = *(float2*)(ks_s + j0 + 8 + qd*2);
    den0 = fmaf(e00, kv0.x, fmaf(e01, kv0.y, fmaf(e10, kv1.x, fmaf(e11, kv1.y, den0))));
    den1 = fmaf(e02, kv0.x, fmaf(e03, kv0.y, fmaf(e12, kv1.x, fmaf(e13, kv1.y, den1))));

    __nv_bfloat16 h00 = __float2bfloat16(e00), h01 = __float2bfloat16(e01);
    __nv_bfloat16 h02 = __float2bfloat16(e02), h03 = __float2bfloat16(e03);
    __nv_bfloat16 h10 = __float2bfloat16(e10), h11 = __float2bfloat16(e11);
    __nv_bfloat16 h12 = __float2bfloat16(e12), h13 = __float2bfloat16(e13);
    uint32_t qa_hi[4] = { packb(h00, h01), packb(h02, h03),
                          packb(h10, h11), packb(h12, h13) };
    uint32_t qa_lo[4] = {
      packb(__float2bfloat16(e00 - __bfloat162float(h00)),
            __float2bfloat16(e01 - __bfloat162float(h01))),
      packb(__float2bfloat16(e02 - __bfloat162float(h02)),
            __float2bfloat16(e03 - __bfloat162float(h03))),
      packb(__float2bfloat16(e10 - __bfloat162float(h10)),
            __float2bfloat16(e11 - __bfloat162float(h11))),
      packb(__float2bfloat16(e12 - __bfloat162float(h12)),
            __float2bfloat16(e13 - __bfloat162float(h13))) };

    const int ch0 = jt * 2;
#pragma unroll
    for (int etp = 0; etp < 4; etp++) {
      uint32_t bh_[4], bl_[4];
      int e = (etp*2 + (lg >> 1))*8 + li;
      int ch = ch0 + (lg & 1);
      uint32_t off = (uint32_t)e*512
                   + (uint32_t)((((ch & 24) | ((ch ^ li) & 7))) << 4);
      ldmx4(bh_, sb + OCHI + off);
      ldmx4(bl_, sb + OCLO + off);
      int et0 = etp*2, et1 = etp*2 + 1;
      mma_bf16(oacc[et0], qa_hi, bh_ + 0, oacc[et0]);
      mma_bf16(oacc[et0], qa_lo, bh_ + 0, oacc[et0]);
      mma_bf16(oacc[et0], qa_hi, bl_ + 0, oacc[et0]);
      mma_bf16(oacc[et1], qa_hi, bh_ + 2, oacc[et1]);
      mma_bf16(oacc[et1], qa_lo, bh_ + 2, oacc[et1]);
      mma_bf16(oacc[et1], qa_hi, bl_ + 2, oacc[et1]);
    }
  }

  den0 += __shfl_xor_sync(0xffffffff, den0, 1);
  den0 += __shfl_xor_sync(0xffffffff, den0, 2);
  den1 += __shfl_xor_sync(0xffffffff, den1, 1);
  den1 += __shfl_xor_sync(0xffffffff, den1, 2);
  float inv0 = 1.f / den0, inv1 = 1.f / den1;

  float* og0 = outg + ((size_t)(bh * T_ + t0 + r0 + grp)) * DH_;
  float* og1 = og0 + 8 * DH_;
#pragma unroll
  for (int et = 0; et < 8; et++) {
    int col = et * 8 + qd * 2;
    *(float2*)(og0 + col) = make_float2(oacc[et][0] * inv0, oacc[et][1] * inv0);
    *(float2*)(og1 + col) = make_float2(oacc[et][2] * inv1, oacc[et][3] * inv1);
  }
}

// ---------------------------------------------------------------------------
extern "C" void kernel_launch(void* const* d_in, const int* in_sizes, int n_in,
                              void* d_out, int out_size) {
  const float* q    = (const float*)d_in[0];
  const float* k    = (const float*)d_in[1];
  const float* v    = (const float*)d_in[2];
  const float* proj = (const float*)d_in[3];
  float* out = (float*)d_out;

  cudaFuncSetAttribute(kernelAB, cudaFuncAttributeMaxDynamicSharedMemorySize, SMEMAB);
  cudaFuncSetAttribute(kernelC,  cudaFuncAttributeMaxDynamicSharedMemorySize, SMEMC);

  kernelAB<<<dim3(8, BH_), 256, SMEMAB>>>(k, v, proj);
  reduce_kernel<<<(BH_*65*NF_ + 255)/256, 256>>>();
  kernelC<<<dim3(T_/128, BH_), 256, SMEMC>>>(q, proj, out);
}